// round 2
// baseline (speedup 1.0000x reference)
#include <cuda_runtime.h>
#include <math.h>

#define N_NODES 50000
#define N_EDGES 800000
#define SCAN_B  1024
#define SCAN_NB ((N_NODES + SCAN_B - 1) / SCAN_B)   // 49

// ---------------- scratch (static device memory; no allocs) ----------------
__device__ int   g_counts[N_NODES];
__device__ int   g_rowptr[N_NODES + 1];
__device__ int   g_cursor[N_NODES];
__device__ int   g_tmp[N_NODES];
__device__ int   g_bsum[SCAN_NB];
__device__ int   g_esrc[N_EDGES];
__device__ float g_ewt[N_EDGES];
__device__ float g_h[2][N_NODES * 64];
__device__ float g_t[N_NODES];
__device__ float g_r[N_NODES];

// ---------------- CSR build ----------------
__global__ void k_zero_counts() {
    int i = blockIdx.x * blockDim.x + threadIdx.x;
    if (i < N_NODES) g_counts[i] = 0;
}

__global__ void k_hist(const int* __restrict__ dst) {
    int e = blockIdx.x * blockDim.x + threadIdx.x;
    if (e < N_EDGES) atomicAdd(&g_counts[dst[e]], 1);
}

__global__ void k_scan_part() {
    __shared__ int s[SCAN_B];
    int tid = threadIdx.x;
    int i = blockIdx.x * SCAN_B + tid;
    int v = (i < N_NODES) ? g_counts[i] : 0;
    s[tid] = v;
    __syncthreads();
    for (int off = 1; off < SCAN_B; off <<= 1) {
        int t = (tid >= off) ? s[tid - off] : 0;
        __syncthreads();
        s[tid] += t;
        __syncthreads();
    }
    if (i < N_NODES) g_tmp[i] = s[tid];
    if (tid == SCAN_B - 1) g_bsum[blockIdx.x] = s[tid];
}

// finalize: each block computes its own offset from g_bsum (warp prefix, no extra launch)
__global__ void k_scan_fin() {
    __shared__ int soff;
    int tid = threadIdx.x;
    if (tid < 32) {
        int v = 0;
        for (int j = tid; j < (int)blockIdx.x; j += 32) v += g_bsum[j];
#pragma unroll
        for (int o = 16; o > 0; o >>= 1) v += __shfl_xor_sync(0xffffffffu, v, o);
        if (tid == 0) soff = v;
    }
    __syncthreads();
    int off = soff;
    int i = blockIdx.x * SCAN_B + tid;
    if (i < N_NODES) {
        int incl = g_tmp[i] + off;
        int excl = incl - g_counts[i];
        g_rowptr[i] = excl;
        g_cursor[i] = excl;
        if (i == N_NODES - 1) g_rowptr[N_NODES] = incl;
    }
}

__global__ void k_scatter(const int* __restrict__ src, const int* __restrict__ dst,
                          const float* __restrict__ ew) {
    int e = blockIdx.x * blockDim.x + threadIdx.x;
    if (e < N_EDGES) {
        int d = dst[e];
        int p = atomicAdd(&g_cursor[d], 1);
        g_esrc[p] = src[e];
        g_ewt[p]  = ew[e];
    }
}

// ---------------- fused layer 0: aggregate(13) + dual-GEMM 13->64 ----------
__global__ __launch_bounds__(256) void k_fused13(
    const float* __restrict__ x,
    const float* __restrict__ Wrel, const float* __restrict__ brel,
    const float* __restrict__ Wroot) {
    __shared__ __align__(16) float sW[2 * 13 * 64];
    __shared__ float sb[64];
    __shared__ float sA[64 * 14];
    int tid = threadIdx.x;
    for (int idx = tid; idx < 13 * 64; idx += 256) {
        sW[idx]           = Wrel[idx];
        sW[13 * 64 + idx] = Wroot[idx];
    }
    if (tid < 64) sb[tid] = brel[tid];

    // aggregation: 8 warps x 8 nodes each
    {
        int wid = tid >> 5, lane = tid & 31;
        for (int i = 0; i < 8; i++) {
            int loc  = wid * 8 + i;
            int node = blockIdx.x * 64 + loc;
            float a = 0.f;
            if (node < N_NODES && lane < 13) {
                int e = g_rowptr[node], ee = g_rowptr[node + 1];
                for (; e + 2 <= ee; e += 2) {
                    int   s0 = __ldg(&g_esrc[e]);     float w0 = __ldg(&g_ewt[e]);
                    int   s1 = __ldg(&g_esrc[e + 1]); float w1 = __ldg(&g_ewt[e + 1]);
                    a += w0 * __ldg(&x[s0 * 13 + lane]) + w1 * __ldg(&x[s1 * 13 + lane]);
                }
                if (e < ee) a += __ldg(&g_ewt[e]) * __ldg(&x[__ldg(&g_esrc[e]) * 13 + lane]);
            }
            if (lane < 13) sA[loc * 14 + lane] = a;
        }
    }
    __syncthreads();

    // dual GEMM: thread = (node local, 16-col group)
    int loc  = tid >> 2;
    int node = blockIdx.x * 64 + loc;
    int cq   = (tid & 3) * 4;     // float4 group base
    int c0   = cq * 4;            // column base
    float acc[16];
#pragma unroll
    for (int j = 0; j < 16; j++) acc[j] = sb[c0 + j];
    const float4* sWrel4  = (const float4*)sW;
    const float4* sWroot4 = (const float4*)(sW + 13 * 64);
    int nc = node < N_NODES ? node : 0;
#pragma unroll
    for (int k = 0; k < 13; k++) {
        float a  = sA[loc * 14 + k];
        float hk = __ldg(&x[nc * 13 + k]);
#pragma unroll
        for (int j = 0; j < 4; j++) {
            float4 wr = sWrel4[k * 16 + cq + j];
            float4 ws = sWroot4[k * 16 + cq + j];
            acc[4 * j + 0] += a * wr.x + hk * ws.x;
            acc[4 * j + 1] += a * wr.y + hk * ws.y;
            acc[4 * j + 2] += a * wr.z + hk * ws.z;
            acc[4 * j + 3] += a * wr.w + hk * ws.w;
        }
    }
    if (node < N_NODES) {
        float4* o4 = (float4*)(g_h[0] + (long)node * 64 + c0);
#pragma unroll
        for (int j = 0; j < 4; j++) {
            float4 v;
            v.x = fmaxf(acc[4 * j + 0], 0.f); v.y = fmaxf(acc[4 * j + 1], 0.f);
            v.z = fmaxf(acc[4 * j + 2], 0.f); v.w = fmaxf(acc[4 * j + 3], 0.f);
            o4[j] = v;
        }
    }
}

// ---------------- fused mid layer: aggregate(64) + dual-GEMM 64->64 --------
// FINAL=true: instead of writing h, fold in layer-4 projection:
//   g_t = relu(h)@Wrel4, g_r = relu(h)@Wroot4 + b4
template <bool FINAL>
__global__ __launch_bounds__(256) void k_fused64(
    const float* __restrict__ Wrel, const float* __restrict__ brel,
    const float* __restrict__ Wroot,
    const float* __restrict__ Wrel4, const float* __restrict__ b4,
    const float* __restrict__ Wroot4,
    int insel, int outsel) {
    extern __shared__ float smem[];
    float* sW = smem;              // 2*64*64 = 8192 floats
    float* sb = smem + 8192;       // 64
    float* sA = smem + 8192 + 64;  // 64*66 = 4224 (pad 66: conflict-free)
    int tid = threadIdx.x;
    {
        const float4* Wr4 = (const float4*)Wrel;
        const float4* Ws4 = (const float4*)Wroot;
        float4* d0 = (float4*)sW;
        float4* d1 = (float4*)(sW + 64 * 64);
        for (int idx = tid; idx < 1024; idx += 256) {
            d0[idx] = Wr4[idx];
            d1[idx] = Ws4[idx];
        }
        if (tid < 64) sb[tid] = brel[tid];
    }

    const float* __restrict__ h = g_h[insel];

    // aggregation phase: 8 warps x 8 nodes; lane covers dims (2*lane, 2*lane+1)
    {
        int wid = tid >> 5, lane = tid & 31;
        for (int i = 0; i < 8; i++) {
            int loc  = wid * 8 + i;
            int node = blockIdx.x * 64 + loc;
            float ax = 0.f, ay = 0.f;
            if (node < N_NODES) {
                int e = g_rowptr[node], ee = g_rowptr[node + 1];
                for (; e + 4 <= ee; e += 4) {
                    int   s0 = __ldg(&g_esrc[e + 0]); float w0 = __ldg(&g_ewt[e + 0]);
                    int   s1 = __ldg(&g_esrc[e + 1]); float w1 = __ldg(&g_ewt[e + 1]);
                    int   s2 = __ldg(&g_esrc[e + 2]); float w2 = __ldg(&g_ewt[e + 2]);
                    int   s3 = __ldg(&g_esrc[e + 3]); float w3 = __ldg(&g_ewt[e + 3]);
                    float2 h0 = __ldg((const float2*)(h + s0 * 64) + lane);
                    float2 h1 = __ldg((const float2*)(h + s1 * 64) + lane);
                    float2 h2 = __ldg((const float2*)(h + s2 * 64) + lane);
                    float2 h3 = __ldg((const float2*)(h + s3 * 64) + lane);
                    ax += w0 * h0.x + w1 * h1.x + w2 * h2.x + w3 * h3.x;
                    ay += w0 * h0.y + w1 * h1.y + w2 * h2.y + w3 * h3.y;
                }
                for (; e < ee; e++) {
                    int   s = __ldg(&g_esrc[e]); float w = __ldg(&g_ewt[e]);
                    float2 hv = __ldg((const float2*)(h + s * 64) + lane);
                    ax += w * hv.x;
                    ay += w * hv.y;
                }
            }
            sA[loc * 66 + 2 * lane]     = ax;
            sA[loc * 66 + 2 * lane + 1] = ay;
        }
    }
    __syncthreads();

    // GEMM phase
    int loc  = tid >> 2;
    int node = blockIdx.x * 64 + loc;
    int cq   = (tid & 3) * 4;
    int c0   = cq * 4;
    float acc[16];
#pragma unroll
    for (int j = 0; j < 16; j++) acc[j] = sb[c0 + j];
    const float4* sWrel4  = (const float4*)sW;
    const float4* sWroot4 = (const float4*)(sW + 64 * 64);
    int nc = node < N_NODES ? node : 0;
    const float4* h4 = (const float4*)(h + (long)nc * 64);
#pragma unroll
    for (int k4 = 0; k4 < 16; k4++) {
        float4 hv = __ldg(h4 + k4);
        float hvv[4] = {hv.x, hv.y, hv.z, hv.w};
#pragma unroll
        for (int kk = 0; kk < 4; kk++) {
            int k = k4 * 4 + kk;
            float a  = sA[loc * 66 + k];
            float hk = hvv[kk];
#pragma unroll
            for (int j = 0; j < 4; j++) {
                float4 wr = sWrel4[k * 16 + cq + j];
                float4 ws = sWroot4[k * 16 + cq + j];
                acc[4 * j + 0] += a * wr.x + hk * ws.x;
                acc[4 * j + 1] += a * wr.y + hk * ws.y;
                acc[4 * j + 2] += a * wr.z + hk * ws.z;
                acc[4 * j + 3] += a * wr.w + hk * ws.w;
            }
        }
    }

    if (FINAL) {
        // acc[jj] is column c0+jj. Project onto Wrel4 / Wroot4, reduce over
        // the node's 4 threads (consecutive lanes) via shfl.
        float pt = 0.f, pr = 0.f;
#pragma unroll
        for (int jj = 0; jj < 16; jj++) {
            float v = fmaxf(acc[jj], 0.f);
            pt += v * __ldg(&Wrel4[c0 + jj]);
            pr += v * __ldg(&Wroot4[c0 + jj]);
        }
        pt += __shfl_xor_sync(0xffffffffu, pt, 1);
        pt += __shfl_xor_sync(0xffffffffu, pt, 2);
        pr += __shfl_xor_sync(0xffffffffu, pr, 1);
        pr += __shfl_xor_sync(0xffffffffu, pr, 2);
        if ((tid & 3) == 0 && node < N_NODES) {
            g_t[node] = pt;
            g_r[node] = pr + __ldg(&b4[0]);
        }
    } else {
        if (node < N_NODES) {
            float4* o4 = (float4*)(g_h[outsel] + (long)node * 64 + c0);
#pragma unroll
            for (int j = 0; j < 4; j++) {
                float4 v;
                v.x = fmaxf(acc[4 * j + 0], 0.f); v.y = fmaxf(acc[4 * j + 1], 0.f);
                v.z = fmaxf(acc[4 * j + 2], 0.f); v.w = fmaxf(acc[4 * j + 3], 0.f);
                o4[j] = v;
            }
        }
    }
}

// ---------------- final: out = sigmoid(segsum(w * t[src]) + r) -------------
__global__ void k_final(float* __restrict__ out) {
    int gw   = (blockIdx.x * blockDim.x + threadIdx.x) >> 5;
    int lane = threadIdx.x & 31;
    if (gw >= N_NODES) return;
    int start = g_rowptr[gw], end = g_rowptr[gw + 1];
    float acc = 0.f;
    for (int e = start + lane; e < end; e += 32)
        acc += __ldg(&g_ewt[e]) * __ldg(&g_t[g_esrc[e]]);
#pragma unroll
    for (int o = 16; o > 0; o >>= 1)
        acc += __shfl_xor_sync(0xffffffffu, acc, o);
    if (lane == 0) {
        float z = acc + g_r[gw];
        out[gw] = 1.f / (1.f + expf(-z));
    }
}

// ---------------- launch ----------------
extern "C" void kernel_launch(void* const* d_in, const int* in_sizes, int n_in,
                              void* d_out, int out_size) {
    const float* x  = (const float*)d_in[0];
    const int*   ei = (const int*)d_in[1];
    const float* ew = (const float*)d_in[2];
    const int* src = ei;
    const int* dst = ei + N_EDGES;

    const float* Wrel[5], * brel[5], * Wroot[5];
    for (int l = 0; l < 5; l++) {
        Wrel[l]  = (const float*)d_in[3 + 3 * l];
        brel[l]  = (const float*)d_in[4 + 3 * l];
        Wroot[l] = (const float*)d_in[5 + 3 * l];
    }
    float* out = (float*)d_out;

    const int SMEM64 = (2 * 64 * 64 + 64 + 64 * 66) * 4;   // 49920 B
    cudaFuncSetAttribute(k_fused64<false>, cudaFuncAttributeMaxDynamicSharedMemorySize, SMEM64);
    cudaFuncSetAttribute(k_fused64<true>,  cudaFuncAttributeMaxDynamicSharedMemorySize, SMEM64);

    const int TB = 256;
    int gN = (N_NODES + TB - 1) / TB;
    int gE = (N_EDGES + TB - 1) / TB;
    int gW = (N_NODES * 32 + TB - 1) / TB;   // warp-per-node grid
    int gG = (N_NODES + 63) / 64;            // fused layer grid

    // CSR build
    k_zero_counts<<<gN, TB>>>();
    k_hist<<<gE, TB>>>(dst);
    k_scan_part<<<SCAN_NB, SCAN_B>>>();
    k_scan_fin<<<SCAN_NB, SCAN_B>>>();
    k_scatter<<<gE, TB>>>(src, dst, ew);

    // layer 0: 13 -> 64
    k_fused13<<<gG, TB>>>(x, Wrel[0], brel[0], Wroot[0]);

    // layers 1-3: 64 -> 64 (layer 3 fuses the 64->1 projection of layer 4)
    k_fused64<false><<<gG, TB, SMEM64>>>(Wrel[1], brel[1], Wroot[1],
                                         nullptr, nullptr, nullptr, 0, 1);
    k_fused64<false><<<gG, TB, SMEM64>>>(Wrel[2], brel[2], Wroot[2],
                                         nullptr, nullptr, nullptr, 1, 0);
    k_fused64<true><<<gG, TB, SMEM64>>>(Wrel[3], brel[3], Wroot[3],
                                        Wrel[4], brel[4], Wroot[4], 0, 0);

    // layer 4 aggregation (scalar) + sigmoid
    k_final<<<gW, TB>>>(out);
}

// round 3
// speedup vs baseline: 1.6018x; 1.6018x over previous
#include <cuda_runtime.h>
#include <math.h>

#define N_NODES 50000
#define N_EDGES 800000
#define SCAN_B  1024
#define SCAN_NB ((N_NODES + SCAN_B - 1) / SCAN_B)   // 49

// ---------------- scratch (static device memory; no allocs) ----------------
__device__ int   g_counts[N_NODES];
__device__ int   g_rowptr[N_NODES + 1];
__device__ int   g_cursor[N_NODES];
__device__ int   g_tmp[N_NODES];
__device__ int   g_bsum[SCAN_NB];
__device__ int2  g_edge[N_EDGES];          // {src, weight-as-int}
__device__ float g_h[2][N_NODES * 64];
__device__ float g_aggr[N_NODES * 64];     // also holds 16-stride layer0 aggr
__device__ float g_t[N_NODES];
__device__ float g_r[N_NODES];

// ---------------- CSR build ----------------
__global__ void k_hist(const int* __restrict__ dst) {
    int e = blockIdx.x * blockDim.x + threadIdx.x;
    if (e < N_EDGES) atomicAdd(&g_counts[dst[e]], 1);
}

__global__ void k_scan_part() {
    __shared__ int s[SCAN_B];
    int tid = threadIdx.x;
    int i = blockIdx.x * SCAN_B + tid;
    int v = (i < N_NODES) ? g_counts[i] : 0;
    s[tid] = v;
    __syncthreads();
    for (int off = 1; off < SCAN_B; off <<= 1) {
        int t = (tid >= off) ? s[tid - off] : 0;
        __syncthreads();
        s[tid] += t;
        __syncthreads();
    }
    if (i < N_NODES) g_tmp[i] = s[tid];
    if (tid == SCAN_B - 1) g_bsum[blockIdx.x] = s[tid];
}

__global__ void k_scan_fin() {
    __shared__ int soff;
    int tid = threadIdx.x;
    if (tid < 32) {
        int v = 0;
        for (int j = tid; j < (int)blockIdx.x; j += 32) v += g_bsum[j];
#pragma unroll
        for (int o = 16; o > 0; o >>= 1) v += __shfl_xor_sync(0xffffffffu, v, o);
        if (tid == 0) soff = v;
    }
    __syncthreads();
    int off = soff;
    int i = blockIdx.x * SCAN_B + tid;
    if (i < N_NODES) {
        int incl = g_tmp[i] + off;
        int excl = incl - g_counts[i];
        g_rowptr[i] = excl;
        g_cursor[i] = excl;
        if (i == N_NODES - 1) g_rowptr[N_NODES] = incl;
    }
}

__global__ void k_scatter(const int* __restrict__ src, const int* __restrict__ dst,
                          const float* __restrict__ ew) {
    int e = blockIdx.x * blockDim.x + threadIdx.x;
    if (e < N_EDGES) {
        int d = dst[e];
        int p = atomicAdd(&g_cursor[d], 1);
        int2 rec;
        rec.x = src[e];
        rec.y = __float_as_int(ew[e]);
        g_edge[p] = rec;
    }
}

// ---------------- aggregation: warp per node ----------------
// mid layers: lane covers dims (2*lane, 2*lane+1); one coalesced 256B row load
__global__ void k_aggr64(int sel) {
    int gw   = (blockIdx.x * blockDim.x + threadIdx.x) >> 5;
    int lane = threadIdx.x & 31;
    if (gw >= N_NODES) return;
    const float* __restrict__ h = g_h[sel];
    int e = g_rowptr[gw], ee = g_rowptr[gw + 1];
    float ax = 0.f, ay = 0.f, bx = 0.f, by = 0.f;
    for (; e + 4 <= ee; e += 4) {
        int2 e0 = __ldg(&g_edge[e + 0]);
        int2 e1 = __ldg(&g_edge[e + 1]);
        int2 e2 = __ldg(&g_edge[e + 2]);
        int2 e3 = __ldg(&g_edge[e + 3]);
        float2 v0 = __ldg((const float2*)(h + e0.x * 64) + lane);
        float2 v1 = __ldg((const float2*)(h + e1.x * 64) + lane);
        float2 v2 = __ldg((const float2*)(h + e2.x * 64) + lane);
        float2 v3 = __ldg((const float2*)(h + e3.x * 64) + lane);
        float w0 = __int_as_float(e0.y), w1 = __int_as_float(e1.y);
        float w2 = __int_as_float(e2.y), w3 = __int_as_float(e3.y);
        ax += w0 * v0.x + w1 * v1.x;
        ay += w0 * v0.y + w1 * v1.y;
        bx += w2 * v2.x + w3 * v3.x;
        by += w2 * v2.y + w3 * v3.y;
    }
    for (; e < ee; e++) {
        int2 er = __ldg(&g_edge[e]);
        float2 v = __ldg((const float2*)(h + er.x * 64) + lane);
        float w = __int_as_float(er.y);
        ax += w * v.x;
        ay += w * v.y;
    }
    float2 o;
    o.x = ax + bx;
    o.y = ay + by;
    *((float2*)(g_aggr + (long)gw * 64) + lane) = o;
}

// layer 0: 13-dim gather, stride-16 padded output
__global__ void k_aggr13(const float* __restrict__ x) {
    int gw   = (blockIdx.x * blockDim.x + threadIdx.x) >> 5;
    int lane = threadIdx.x & 31;
    if (gw >= N_NODES) return;
    int e = g_rowptr[gw], ee = g_rowptr[gw + 1];
    float a = 0.f, b = 0.f;
    if (lane < 13) {
        for (; e + 2 <= ee; e += 2) {
            int2 e0 = __ldg(&g_edge[e + 0]);
            int2 e1 = __ldg(&g_edge[e + 1]);
            a += __int_as_float(e0.y) * __ldg(&x[e0.x * 13 + lane]);
            b += __int_as_float(e1.y) * __ldg(&x[e1.x * 13 + lane]);
        }
        if (e < ee) {
            int2 er = __ldg(&g_edge[e]);
            a += __int_as_float(er.y) * __ldg(&x[er.x * 13 + lane]);
        }
        g_aggr[gw * 16 + lane] = a + b;
    }
}

// ---------------- GEMM 13->64: 64 nodes/block, 1 node/thread x 16 cols ------
__global__ __launch_bounds__(256) void k_gemm13(
    const float* __restrict__ x,
    const float* __restrict__ Wrel, const float* __restrict__ brel,
    const float* __restrict__ Wroot) {
    __shared__ __align__(16) float sW[2 * 13 * 64];
    __shared__ float sb[64];
    int tid = threadIdx.x;
    for (int idx = tid; idx < 13 * 64; idx += 256) {
        sW[idx]           = Wrel[idx];
        sW[13 * 64 + idx] = Wroot[idx];
    }
    if (tid < 64) sb[tid] = brel[tid];
    __syncthreads();

    int node = blockIdx.x * 64 + (tid >> 2);
    int cq   = (tid & 3) * 4;
    int c0   = cq * 4;
    if (node >= N_NODES) return;
    float acc[16];
#pragma unroll
    for (int j = 0; j < 16; j++) acc[j] = sb[c0 + j];
    const float4* sWrel4  = (const float4*)sW;
    const float4* sWroot4 = (const float4*)(sW + 13 * 64);
#pragma unroll
    for (int k = 0; k < 13; k++) {
        float a  = __ldg(&g_aggr[node * 16 + k]);
        float hk = __ldg(&x[node * 13 + k]);
#pragma unroll
        for (int j = 0; j < 4; j++) {
            float4 wr = sWrel4[k * 16 + cq + j];
            float4 ws = sWroot4[k * 16 + cq + j];
            acc[4 * j + 0] += a * wr.x + hk * ws.x;
            acc[4 * j + 1] += a * wr.y + hk * ws.y;
            acc[4 * j + 2] += a * wr.z + hk * ws.z;
            acc[4 * j + 3] += a * wr.w + hk * ws.w;
        }
    }
    float4* o4 = (float4*)(g_h[0] + (long)node * 64 + c0);
#pragma unroll
    for (int j = 0; j < 4; j++) {
        float4 v;
        v.x = fmaxf(acc[4 * j + 0], 0.f); v.y = fmaxf(acc[4 * j + 1], 0.f);
        v.z = fmaxf(acc[4 * j + 2], 0.f); v.w = fmaxf(acc[4 * j + 3], 0.f);
        o4[j] = v;
    }
}

// ---------------- GEMM 64->64: 128 nodes/block, 2 nodes/thread x 16 cols ----
// FINAL: fold layer-4 projection (g_t = relu(h)@Wrel4, g_r = relu(h)@Wroot4+b4)
template <bool FINAL>
__global__ __launch_bounds__(256) void k_gemm64(
    const float* __restrict__ Wrel, const float* __restrict__ brel,
    const float* __restrict__ Wroot,
    const float* __restrict__ Wrel4, const float* __restrict__ b4,
    const float* __restrict__ Wroot4,
    int insel, int outsel) {
    __shared__ __align__(16) float sW[2 * 64 * 64];
    __shared__ float sb[64];
    int tid = threadIdx.x;
    {
        const float4* Wr4 = (const float4*)Wrel;
        const float4* Ws4 = (const float4*)Wroot;
        float4* d0 = (float4*)sW;
        float4* d1 = (float4*)(sW + 64 * 64);
        for (int idx = tid; idx < 1024; idx += 256) {
            d0[idx] = Wr4[idx];
            d1[idx] = Ws4[idx];
        }
        if (tid < 64) sb[tid] = brel[tid];
    }
    __syncthreads();

    const float* __restrict__ h = g_h[insel];
    int ng   = tid >> 2;                       // 0..63 node pair group
    int n0   = blockIdx.x * 128 + ng * 2;      // first node of pair
    int cq   = (tid & 3) * 4;
    int c0   = cq * 4;
    bool v0ok = (n0 < N_NODES), v1ok = (n0 + 1 < N_NODES);
    int m0 = v0ok ? n0 : 0, m1 = v1ok ? (n0 + 1) : 0;

    float acc0[16], acc1[16];
#pragma unroll
    for (int j = 0; j < 16; j++) { acc0[j] = sb[c0 + j]; acc1[j] = sb[c0 + j]; }

    const float4* sWrel4  = (const float4*)sW;
    const float4* sWroot4 = (const float4*)(sW + 64 * 64);
    const float4* a0p = (const float4*)(g_aggr + (long)m0 * 64);
    const float4* a1p = (const float4*)(g_aggr + (long)m1 * 64);
    const float4* h0p = (const float4*)(h + (long)m0 * 64);
    const float4* h1p = (const float4*)(h + (long)m1 * 64);

#pragma unroll 4
    for (int k4 = 0; k4 < 16; k4++) {
        float4 a0 = __ldg(a0p + k4), a1 = __ldg(a1p + k4);
        float4 h0 = __ldg(h0p + k4), h1 = __ldg(h1p + k4);
        float a0v[4] = {a0.x, a0.y, a0.z, a0.w};
        float a1v[4] = {a1.x, a1.y, a1.z, a1.w};
        float h0v[4] = {h0.x, h0.y, h0.z, h0.w};
        float h1v[4] = {h1.x, h1.y, h1.z, h1.w};
#pragma unroll
        for (int kk = 0; kk < 4; kk++) {
            int k = k4 * 4 + kk;
#pragma unroll
            for (int j = 0; j < 4; j++) {
                float4 wr = sWrel4[k * 16 + cq + j];
                float4 ws = sWroot4[k * 16 + cq + j];
                acc0[4 * j + 0] += a0v[kk] * wr.x + h0v[kk] * ws.x;
                acc0[4 * j + 1] += a0v[kk] * wr.y + h0v[kk] * ws.y;
                acc0[4 * j + 2] += a0v[kk] * wr.z + h0v[kk] * ws.z;
                acc0[4 * j + 3] += a0v[kk] * wr.w + h0v[kk] * ws.w;
                acc1[4 * j + 0] += a1v[kk] * wr.x + h1v[kk] * ws.x;
                acc1[4 * j + 1] += a1v[kk] * wr.y + h1v[kk] * ws.y;
                acc1[4 * j + 2] += a1v[kk] * wr.z + h1v[kk] * ws.z;
                acc1[4 * j + 3] += a1v[kk] * wr.w + h1v[kk] * ws.w;
            }
        }
    }

    if (FINAL) {
        float pt0 = 0.f, pr0 = 0.f, pt1 = 0.f, pr1 = 0.f;
#pragma unroll
        for (int jj = 0; jj < 16; jj++) {
            float wr4 = __ldg(&Wrel4[c0 + jj]);
            float ws4 = __ldg(&Wroot4[c0 + jj]);
            float u0 = fmaxf(acc0[jj], 0.f);
            float u1 = fmaxf(acc1[jj], 0.f);
            pt0 += u0 * wr4; pr0 += u0 * ws4;
            pt1 += u1 * wr4; pr1 += u1 * ws4;
        }
        pt0 += __shfl_xor_sync(0xffffffffu, pt0, 1);
        pt0 += __shfl_xor_sync(0xffffffffu, pt0, 2);
        pr0 += __shfl_xor_sync(0xffffffffu, pr0, 1);
        pr0 += __shfl_xor_sync(0xffffffffu, pr0, 2);
        pt1 += __shfl_xor_sync(0xffffffffu, pt1, 1);
        pt1 += __shfl_xor_sync(0xffffffffu, pt1, 2);
        pr1 += __shfl_xor_sync(0xffffffffu, pr1, 1);
        pr1 += __shfl_xor_sync(0xffffffffu, pr1, 2);
        float bb = __ldg(&b4[0]);
        if ((tid & 3) == 0) {
            if (v0ok) { g_t[n0] = pt0; g_r[n0] = pr0 + bb; }
            if (v1ok) { g_t[n0 + 1] = pt1; g_r[n0 + 1] = pr1 + bb; }
        }
    } else {
        float* ob = g_h[outsel];
        if (v0ok) {
            float4* o4 = (float4*)(ob + (long)n0 * 64 + c0);
#pragma unroll
            for (int j = 0; j < 4; j++) {
                float4 v;
                v.x = fmaxf(acc0[4 * j + 0], 0.f); v.y = fmaxf(acc0[4 * j + 1], 0.f);
                v.z = fmaxf(acc0[4 * j + 2], 0.f); v.w = fmaxf(acc0[4 * j + 3], 0.f);
                o4[j] = v;
            }
        }
        if (v1ok) {
            float4* o4 = (float4*)(ob + (long)(n0 + 1) * 64 + c0);
#pragma unroll
            for (int j = 0; j < 4; j++) {
                float4 v;
                v.x = fmaxf(acc1[4 * j + 0], 0.f); v.y = fmaxf(acc1[4 * j + 1], 0.f);
                v.z = fmaxf(acc1[4 * j + 2], 0.f); v.w = fmaxf(acc1[4 * j + 3], 0.f);
                o4[j] = v;
            }
        }
    }
}

// ---------------- final: out = sigmoid(segsum(w * t[src]) + r) -------------
__global__ void k_final(float* __restrict__ out) {
    int gw   = (blockIdx.x * blockDim.x + threadIdx.x) >> 5;
    int lane = threadIdx.x & 31;
    if (gw >= N_NODES) return;
    int start = g_rowptr[gw], end = g_rowptr[gw + 1];
    float acc = 0.f;
    for (int e = start + lane; e < end; e += 32) {
        int2 er = __ldg(&g_edge[e]);
        acc += __int_as_float(er.y) * __ldg(&g_t[er.x]);
    }
#pragma unroll
    for (int o = 16; o > 0; o >>= 1)
        acc += __shfl_xor_sync(0xffffffffu, acc, o);
    if (lane == 0) {
        float z = acc + g_r[gw];
        out[gw] = 1.f / (1.f + expf(-z));
    }
}

// ---------------- launch ----------------
extern "C" void kernel_launch(void* const* d_in, const int* in_sizes, int n_in,
                              void* d_out, int out_size) {
    const float* x  = (const float*)d_in[0];
    const int*   ei = (const int*)d_in[1];
    const float* ew = (const float*)d_in[2];
    const int* src = ei;
    const int* dst = ei + N_EDGES;

    const float* Wrel[5], * brel[5], * Wroot[5];
    for (int l = 0; l < 5; l++) {
        Wrel[l]  = (const float*)d_in[3 + 3 * l];
        brel[l]  = (const float*)d_in[4 + 3 * l];
        Wroot[l] = (const float*)d_in[5 + 3 * l];
    }
    float* out = (float*)d_out;

    void* counts_ptr = nullptr;
    cudaGetSymbolAddress(&counts_ptr, g_counts);

    const int TB = 256;
    int gE  = (N_EDGES + TB - 1) / TB;
    int gW  = (N_NODES * 32 + TB - 1) / TB;  // warp-per-node grid
    int g64 = (N_NODES + 63) / 64;           // gemm13 grid
    int g128 = (N_NODES + 127) / 128;        // gemm64 grid

    // CSR build
    cudaMemsetAsync(counts_ptr, 0, N_NODES * sizeof(int));
    k_hist<<<gE, TB>>>(dst);
    k_scan_part<<<SCAN_NB, SCAN_B>>>();
    k_scan_fin<<<SCAN_NB, SCAN_B>>>();
    k_scatter<<<gE, TB>>>(src, dst, ew);

    // layer 0: 13 -> 64
    k_aggr13<<<gW, TB>>>(x);
    k_gemm13<<<g64, TB>>>(x, Wrel[0], brel[0], Wroot[0]);

    // layers 1-3: 64 -> 64 (layer 3 folds the 64->1 projection of layer 4)
    k_aggr64<<<gW, TB>>>(0);
    k_gemm64<false><<<g128, TB>>>(Wrel[1], brel[1], Wroot[1],
                                  nullptr, nullptr, nullptr, 0, 1);
    k_aggr64<<<gW, TB>>>(1);
    k_gemm64<false><<<g128, TB>>>(Wrel[2], brel[2], Wroot[2],
                                  nullptr, nullptr, nullptr, 1, 0);
    k_aggr64<<<gW, TB>>>(0);
    k_gemm64<true><<<g128, TB>>>(Wrel[3], brel[3], Wroot[3],
                                 Wrel[4], brel[4], Wroot[4], 0, 0);

    // layer 4 aggregation (scalar) + sigmoid
    k_final<<<gW, TB>>>(out);
}

// round 4
// speedup vs baseline: 2.2889x; 1.4289x over previous
#include <cuda_runtime.h>
#include <math.h>

#define N_NODES 50000
#define N_EDGES 800000
#define SCAN_B  1024
#define SCAN_NB ((N_NODES + SCAN_B - 1) / SCAN_B)   // 49

// ---------------- scratch (static device memory; no allocs) ----------------
__device__ int   g_counts[N_NODES];
__device__ int   g_rowptr[N_NODES + 1];
__device__ int   g_cursor[N_NODES];
__device__ int   g_tmp[N_NODES];
__device__ int   g_bsum[SCAN_NB];
__device__ int2  g_edge[N_EDGES];          // {src, weight-as-int}
__device__ float g_h[2][N_NODES * 64];
__device__ float g_aggr[N_NODES * 64];     // also holds 16-stride layer0 aggr
__device__ float g_t[N_NODES];
__device__ float g_r[N_NODES];

// ---------------- helpers ----------------
__device__ __forceinline__ unsigned bf16_rn(float f) {
    unsigned u = __float_as_uint(f);
    return (u + 0x7fffu + ((u >> 16) & 1u)) >> 16;
}

__device__ __forceinline__ void mma_bf16(float* c,
                                         unsigned a0, unsigned a1, unsigned a2, unsigned a3,
                                         unsigned b0, unsigned b1) {
    asm volatile(
        "mma.sync.aligned.m16n8k16.row.col.f32.bf16.bf16.f32 "
        "{%0,%1,%2,%3}, {%4,%5,%6,%7}, {%8,%9}, {%0,%1,%2,%3};\n"
        : "+f"(c[0]), "+f"(c[1]), "+f"(c[2]), "+f"(c[3])
        : "r"(a0), "r"(a1), "r"(a2), "r"(a3), "r"(b0), "r"(b1));
}

// ---------------- CSR build ----------------
__global__ void k_hist(const int* __restrict__ dst) {
    int e = blockIdx.x * blockDim.x + threadIdx.x;
    if (e < N_EDGES) atomicAdd(&g_counts[dst[e]], 1);
}

__global__ void k_scan_part() {
    __shared__ int s[SCAN_B];
    int tid = threadIdx.x;
    int i = blockIdx.x * SCAN_B + tid;
    int v = (i < N_NODES) ? g_counts[i] : 0;
    s[tid] = v;
    __syncthreads();
    for (int off = 1; off < SCAN_B; off <<= 1) {
        int t = (tid >= off) ? s[tid - off] : 0;
        __syncthreads();
        s[tid] += t;
        __syncthreads();
    }
    if (i < N_NODES) g_tmp[i] = s[tid];
    if (tid == SCAN_B - 1) g_bsum[blockIdx.x] = s[tid];
}

__global__ void k_scan_fin() {
    __shared__ int soff;
    int tid = threadIdx.x;
    if (tid < 32) {
        int v = 0;
        for (int j = tid; j < (int)blockIdx.x; j += 32) v += g_bsum[j];
#pragma unroll
        for (int o = 16; o > 0; o >>= 1) v += __shfl_xor_sync(0xffffffffu, v, o);
        if (tid == 0) soff = v;
    }
    __syncthreads();
    int off = soff;
    int i = blockIdx.x * SCAN_B + tid;
    if (i < N_NODES) {
        int incl = g_tmp[i] + off;
        int excl = incl - g_counts[i];
        g_rowptr[i] = excl;
        g_cursor[i] = excl;
        if (i == N_NODES - 1) g_rowptr[N_NODES] = incl;
    }
}

__global__ void k_scatter(const int* __restrict__ src, const int* __restrict__ dst,
                          const float* __restrict__ ew) {
    int e = blockIdx.x * blockDim.x + threadIdx.x;
    if (e < N_EDGES) {
        int d = dst[e];
        int p = atomicAdd(&g_cursor[d], 1);
        int2 rec;
        rec.x = src[e];
        rec.y = __float_as_int(ew[e]);
        g_edge[p] = rec;
    }
}

// ---------------- aggregation: warp per node ----------------
__global__ void k_aggr64(int sel) {
    int gw   = (blockIdx.x * blockDim.x + threadIdx.x) >> 5;
    int lane = threadIdx.x & 31;
    if (gw >= N_NODES) return;
    const float* __restrict__ h = g_h[sel];
    int e = g_rowptr[gw], ee = g_rowptr[gw + 1];
    float ax = 0.f, ay = 0.f, bx = 0.f, by = 0.f;
    for (; e + 4 <= ee; e += 4) {
        int2 e0 = __ldg(&g_edge[e + 0]);
        int2 e1 = __ldg(&g_edge[e + 1]);
        int2 e2 = __ldg(&g_edge[e + 2]);
        int2 e3 = __ldg(&g_edge[e + 3]);
        float2 v0 = __ldg((const float2*)(h + e0.x * 64) + lane);
        float2 v1 = __ldg((const float2*)(h + e1.x * 64) + lane);
        float2 v2 = __ldg((const float2*)(h + e2.x * 64) + lane);
        float2 v3 = __ldg((const float2*)(h + e3.x * 64) + lane);
        float w0 = __int_as_float(e0.y), w1 = __int_as_float(e1.y);
        float w2 = __int_as_float(e2.y), w3 = __int_as_float(e3.y);
        ax += w0 * v0.x + w1 * v1.x;
        ay += w0 * v0.y + w1 * v1.y;
        bx += w2 * v2.x + w3 * v3.x;
        by += w2 * v2.y + w3 * v3.y;
    }
    for (; e < ee; e++) {
        int2 er = __ldg(&g_edge[e]);
        float2 v = __ldg((const float2*)(h + er.x * 64) + lane);
        float w = __int_as_float(er.y);
        ax += w * v.x;
        ay += w * v.y;
    }
    float2 o;
    o.x = ax + bx;
    o.y = ay + by;
    *((float2*)(g_aggr + (long)gw * 64) + lane) = o;
}

__global__ void k_aggr13(const float* __restrict__ x) {
    int gw   = (blockIdx.x * blockDim.x + threadIdx.x) >> 5;
    int lane = threadIdx.x & 31;
    if (gw >= N_NODES) return;
    int e = g_rowptr[gw], ee = g_rowptr[gw + 1];
    float a = 0.f, b = 0.f;
    if (lane < 13) {
        for (; e + 2 <= ee; e += 2) {
            int2 e0 = __ldg(&g_edge[e + 0]);
            int2 e1 = __ldg(&g_edge[e + 1]);
            a += __int_as_float(e0.y) * __ldg(&x[e0.x * 13 + lane]);
            b += __int_as_float(e1.y) * __ldg(&x[e1.x * 13 + lane]);
        }
        if (e < ee) {
            int2 er = __ldg(&g_edge[e]);
            a += __int_as_float(er.y) * __ldg(&x[er.x * 13 + lane]);
        }
        g_aggr[gw * 16 + lane] = a + b;
    }
}

// ---------------- GEMM 13->64 (FFMA; small) --------------------------------
__global__ __launch_bounds__(256) void k_gemm13(
    const float* __restrict__ x,
    const float* __restrict__ Wrel, const float* __restrict__ brel,
    const float* __restrict__ Wroot) {
    __shared__ __align__(16) float sW[2 * 13 * 64];
    __shared__ float sb[64];
    int tid = threadIdx.x;
    for (int idx = tid; idx < 13 * 64; idx += 256) {
        sW[idx]           = Wrel[idx];
        sW[13 * 64 + idx] = Wroot[idx];
    }
    if (tid < 64) sb[tid] = brel[tid];
    __syncthreads();

    int node = blockIdx.x * 64 + (tid >> 2);
    int cq   = (tid & 3) * 4;
    int c0   = cq * 4;
    if (node >= N_NODES) return;
    float acc[16];
#pragma unroll
    for (int j = 0; j < 16; j++) acc[j] = sb[c0 + j];
    const float4* sWrel4  = (const float4*)sW;
    const float4* sWroot4 = (const float4*)(sW + 13 * 64);
#pragma unroll
    for (int k = 0; k < 13; k++) {
        float a  = __ldg(&g_aggr[node * 16 + k]);
        float hk = __ldg(&x[node * 13 + k]);
#pragma unroll
        for (int j = 0; j < 4; j++) {
            float4 wr = sWrel4[k * 16 + cq + j];
            float4 ws = sWroot4[k * 16 + cq + j];
            acc[4 * j + 0] += a * wr.x + hk * ws.x;
            acc[4 * j + 1] += a * wr.y + hk * ws.y;
            acc[4 * j + 2] += a * wr.z + hk * ws.z;
            acc[4 * j + 3] += a * wr.w + hk * ws.w;
        }
    }
    float4* o4 = (float4*)(g_h[0] + (long)node * 64 + c0);
#pragma unroll
    for (int j = 0; j < 4; j++) {
        float4 v;
        v.x = fmaxf(acc[4 * j + 0], 0.f); v.y = fmaxf(acc[4 * j + 1], 0.f);
        v.z = fmaxf(acc[4 * j + 2], 0.f); v.w = fmaxf(acc[4 * j + 3], 0.f);
        o4[j] = v;
    }
}

// ---------------- GEMM 64->64 via bf16 3-term MMA --------------------------
// Block: 256 thr = 8 warps x 16 nodes = 128 nodes. A = [aggr | h] (K=128),
// W = [Wrel ; Wroot] (128x64). hi/lo bf16 split in smem, fp32 accumulate.
// FINAL: fold layer-4 projection (g_t = relu(h)@Wrel4, g_r = relu(h)@Wroot4+b4)
#define AW 68   // padded word stride (bank-conflict-free)
template <bool FINAL>
__global__ __launch_bounds__(256) void k_gemm64_mma(
    const float* __restrict__ Wrel, const float* __restrict__ brel,
    const float* __restrict__ Wroot,
    const float* __restrict__ Wrel4, const float* __restrict__ b4,
    const float* __restrict__ Wroot4,
    int insel, int outsel) {
    extern __shared__ unsigned smem_u[];
    unsigned* sAhi = smem_u;                    // 128*AW
    unsigned* sAlo = sAhi + 128 * AW;           // 128*AW
    unsigned* sWhi = sAlo + 128 * AW;           // 64*AW
    unsigned* sWlo = sWhi + 64 * AW;            // 64*AW
    float*    sb   = (float*)(sWlo + 64 * AW);  // 64

    int tid = threadIdx.x;
    const float* __restrict__ hin = g_h[insel];
    int nbase = blockIdx.x * 128;

    if (tid < 64) sb[tid] = brel[tid];

    // stage W transposed: sW[col][w], element pair k = 2w, 2w+1
    for (int p = tid; p < 64 * 64; p += 256) {
        int col = p >> 6, w = p & 63;
        int k = 2 * w;
        float f0, f1;
        if (k < 64) { f0 = __ldg(&Wrel[k * 64 + col]);        f1 = __ldg(&Wrel[(k + 1) * 64 + col]); }
        else        { f0 = __ldg(&Wroot[(k - 64) * 64 + col]); f1 = __ldg(&Wroot[(k - 63) * 64 + col]); }
        unsigned h0 = bf16_rn(f0), h1 = bf16_rn(f1);
        float r0 = f0 - __uint_as_float(h0 << 16);
        float r1 = f1 - __uint_as_float(h1 << 16);
        sWhi[col * AW + w] = h0 | (h1 << 16);
        sWlo[col * AW + w] = bf16_rn(r0) | (bf16_rn(r1) << 16);
    }
    // stage A: aggr -> words 0..31, h -> words 32..63
    for (int p = tid; p < 128 * 32; p += 256) {
        int ln = p >> 5, w = p & 31;
        int node = nbase + ln;
        if (node >= N_NODES) node = N_NODES - 1;
        float2 va = *(const float2*)(g_aggr + (size_t)node * 64 + 2 * w);
        float2 vh = *(const float2*)(hin    + (size_t)node * 64 + 2 * w);
        {
            unsigned h0 = bf16_rn(va.x), h1 = bf16_rn(va.y);
            sAhi[ln * AW + w] = h0 | (h1 << 16);
            sAlo[ln * AW + w] = bf16_rn(va.x - __uint_as_float(h0 << 16)) |
                                (bf16_rn(va.y - __uint_as_float(h1 << 16)) << 16);
        }
        {
            unsigned h0 = bf16_rn(vh.x), h1 = bf16_rn(vh.y);
            sAhi[ln * AW + 32 + w] = h0 | (h1 << 16);
            sAlo[ln * AW + 32 + w] = bf16_rn(vh.x - __uint_as_float(h0 << 16)) |
                                     (bf16_rn(vh.y - __uint_as_float(h1 << 16)) << 16);
        }
    }
    __syncthreads();

    int warp = tid >> 5, lane = tid & 31;
    int r = lane >> 2, q = lane & 3;
    int mb = warp * 16;

    float acc[8][4];
#pragma unroll
    for (int j = 0; j < 8; j++) {
        float b0 = sb[j * 8 + 2 * q], b1 = sb[j * 8 + 2 * q + 1];
        acc[j][0] = b0; acc[j][1] = b1; acc[j][2] = b0; acc[j][3] = b1;
    }

    int arow0 = (mb + r) * AW, arow1 = (mb + r + 8) * AW;
#pragma unroll
    for (int ks = 0; ks < 8; ks++) {
        int kw = ks * 8 + q;
        unsigned ah0 = sAhi[arow0 + kw],     ah1 = sAhi[arow1 + kw];
        unsigned ah2 = sAhi[arow0 + kw + 4], ah3 = sAhi[arow1 + kw + 4];
        unsigned al0 = sAlo[arow0 + kw],     al1 = sAlo[arow1 + kw];
        unsigned al2 = sAlo[arow0 + kw + 4], al3 = sAlo[arow1 + kw + 4];
#pragma unroll
        for (int j = 0; j < 8; j++) {
            int brow = (j * 8 + r) * AW + ks * 8 + q;
            unsigned bh0 = sWhi[brow], bh1 = sWhi[brow + 4];
            unsigned bl0 = sWlo[brow], bl1 = sWlo[brow + 4];
            mma_bf16(acc[j], ah0, ah1, ah2, ah3, bh0, bh1);
            mma_bf16(acc[j], ah0, ah1, ah2, ah3, bl0, bl1);
            mma_bf16(acc[j], al0, al1, al2, al3, bh0, bh1);
        }
    }

    int n0 = nbase + mb + r;      // row of c0/c1
    int n1 = n0 + 8;              // row of c2/c3
    if (FINAL) {
        float pt0 = 0.f, pr0 = 0.f, pt1 = 0.f, pr1 = 0.f;
#pragma unroll
        for (int j = 0; j < 8; j++) {
            int c = j * 8 + 2 * q;
            float w0 = __ldg(&Wrel4[c]),  w1 = __ldg(&Wrel4[c + 1]);
            float s0 = __ldg(&Wroot4[c]), s1 = __ldg(&Wroot4[c + 1]);
            float u;
            u = fmaxf(acc[j][0], 0.f); pt0 += u * w0; pr0 += u * s0;
            u = fmaxf(acc[j][1], 0.f); pt0 += u * w1; pr0 += u * s1;
            u = fmaxf(acc[j][2], 0.f); pt1 += u * w0; pr1 += u * s0;
            u = fmaxf(acc[j][3], 0.f); pt1 += u * w1; pr1 += u * s1;
        }
        pt0 += __shfl_xor_sync(0xffffffffu, pt0, 1);
        pt0 += __shfl_xor_sync(0xffffffffu, pt0, 2);
        pr0 += __shfl_xor_sync(0xffffffffu, pr0, 1);
        pr0 += __shfl_xor_sync(0xffffffffu, pr0, 2);
        pt1 += __shfl_xor_sync(0xffffffffu, pt1, 1);
        pt1 += __shfl_xor_sync(0xffffffffu, pt1, 2);
        pr1 += __shfl_xor_sync(0xffffffffu, pr1, 1);
        pr1 += __shfl_xor_sync(0xffffffffu, pr1, 2);
        float bb = __ldg(&b4[0]);
        if (q == 0) {
            if (n0 < N_NODES) { g_t[n0] = pt0; g_r[n0] = pr0 + bb; }
            if (n1 < N_NODES) { g_t[n1] = pt1; g_r[n1] = pr1 + bb; }
        }
    } else {
        float* ob = g_h[outsel];
#pragma unroll
        for (int j = 0; j < 8; j++) {
            int c = j * 8 + 2 * q;
            if (n0 < N_NODES)
                *(float2*)(ob + (size_t)n0 * 64 + c) =
                    make_float2(fmaxf(acc[j][0], 0.f), fmaxf(acc[j][1], 0.f));
            if (n1 < N_NODES)
                *(float2*)(ob + (size_t)n1 * 64 + c) =
                    make_float2(fmaxf(acc[j][2], 0.f), fmaxf(acc[j][3], 0.f));
        }
    }
}

// ---------------- final: out = sigmoid(segsum(w * t[src]) + r) -------------
__global__ void k_final(float* __restrict__ out) {
    int gw   = (blockIdx.x * blockDim.x + threadIdx.x) >> 5;
    int lane = threadIdx.x & 31;
    if (gw >= N_NODES) return;
    int start = g_rowptr[gw], end = g_rowptr[gw + 1];
    float acc = 0.f;
    for (int e = start + lane; e < end; e += 32) {
        int2 er = __ldg(&g_edge[e]);
        acc += __int_as_float(er.y) * __ldg(&g_t[er.x]);
    }
#pragma unroll
    for (int o = 16; o > 0; o >>= 1)
        acc += __shfl_xor_sync(0xffffffffu, acc, o);
    if (lane == 0) {
        float z = acc + g_r[gw];
        out[gw] = 1.f / (1.f + expf(-z));
    }
}

// ---------------- launch ----------------
extern "C" void kernel_launch(void* const* d_in, const int* in_sizes, int n_in,
                              void* d_out, int out_size) {
    const float* x  = (const float*)d_in[0];
    const int*   ei = (const int*)d_in[1];
    const float* ew = (const float*)d_in[2];
    const int* src = ei;
    const int* dst = ei + N_EDGES;

    const float* Wrel[5], * brel[5], * Wroot[5];
    for (int l = 0; l < 5; l++) {
        Wrel[l]  = (const float*)d_in[3 + 3 * l];
        brel[l]  = (const float*)d_in[4 + 3 * l];
        Wroot[l] = (const float*)d_in[5 + 3 * l];
    }
    float* out = (float*)d_out;

    void* counts_ptr = nullptr;
    cudaGetSymbolAddress(&counts_ptr, g_counts);

    const int SMEM_MMA = (128 * AW * 2 + 64 * AW * 2 + 64) * 4;   // 104704 B
    cudaFuncSetAttribute(k_gemm64_mma<false>,
                         cudaFuncAttributeMaxDynamicSharedMemorySize, SMEM_MMA);
    cudaFuncSetAttribute(k_gemm64_mma<true>,
                         cudaFuncAttributeMaxDynamicSharedMemorySize, SMEM_MMA);

    const int TB = 256;
    int gE   = (N_EDGES + TB - 1) / TB;
    int gW   = (N_NODES * 32 + TB - 1) / TB;  // warp-per-node grid
    int g64  = (N_NODES + 63) / 64;           // gemm13 grid
    int g128 = (N_NODES + 127) / 128;         // gemm64 grid

    // CSR build
    cudaMemsetAsync(counts_ptr, 0, N_NODES * sizeof(int));
    k_hist<<<gE, TB>>>(dst);
    k_scan_part<<<SCAN_NB, SCAN_B>>>();
    k_scan_fin<<<SCAN_NB, SCAN_B>>>();
    k_scatter<<<gE, TB>>>(src, dst, ew);

    // layer 0: 13 -> 64
    k_aggr13<<<gW, TB>>>(x);
    k_gemm13<<<g64, TB>>>(x, Wrel[0], brel[0], Wroot[0]);

    // layers 1-3: 64 -> 64 (layer 3 folds the 64->1 projection of layer 4)
    k_aggr64<<<gW, TB>>>(0);
    k_gemm64_mma<false><<<g128, TB, SMEM_MMA>>>(Wrel[1], brel[1], Wroot[1],
                                                nullptr, nullptr, nullptr, 0, 1);
    k_aggr64<<<gW, TB>>>(1);
    k_gemm64_mma<false><<<g128, TB, SMEM_MMA>>>(Wrel[2], brel[2], Wroot[2],
                                                nullptr, nullptr, nullptr, 1, 0);
    k_aggr64<<<gW, TB>>>(0);
    k_gemm64_mma<true><<<g128, TB, SMEM_MMA>>>(Wrel[3], brel[3], Wroot[3],
                                               Wrel[4], brel[4], Wroot[4], 0, 0);

    // layer 4 aggregation (scalar) + sigmoid
    k_final<<<gW, TB>>>(out);
}

// round 5
// speedup vs baseline: 2.4323x; 1.0627x over previous
#include <cuda_runtime.h>
#include <math.h>

#define N_NODES 50000
#define N_EDGES 800000
#define SCAN_B  1024
#define SCAN_NB ((N_NODES + SCAN_B - 1) / SCAN_B)   // 49

// griddepcontrol (PDL): trigger lets dependents launch early; wait blocks until
// the immediate predecessor kernel's memory is visible.
#define PDL_TRIGGER() asm volatile("griddepcontrol.launch_dependents;" ::: "memory")
#define PDL_WAIT()    asm volatile("griddepcontrol.wait;" ::: "memory")

// ---------------- scratch (static device memory; no allocs) ----------------
__device__ int   g_counts[N_NODES];
__device__ int   g_rowptr[N_NODES + 1];
__device__ int   g_cursor[N_NODES];
__device__ int   g_tmp[N_NODES];
__device__ int   g_bsum[SCAN_NB];
__device__ int2  g_edge[N_EDGES];          // {src, weight-as-int}
__device__ float g_h[2][N_NODES * 64];
__device__ float g_aggr[N_NODES * 64];     // also holds 16-stride layer0 aggr
__device__ float g_t[N_NODES];
__device__ float g_r[N_NODES];

// ---------------- helpers ----------------
__device__ __forceinline__ unsigned bf16_rn(float f) {
    unsigned u = __float_as_uint(f);
    return (u + 0x7fffu + ((u >> 16) & 1u)) >> 16;
}

__device__ __forceinline__ void mma_bf16(float* c,
                                         unsigned a0, unsigned a1, unsigned a2, unsigned a3,
                                         unsigned b0, unsigned b1) {
    asm volatile(
        "mma.sync.aligned.m16n8k16.row.col.f32.bf16.bf16.f32 "
        "{%0,%1,%2,%3}, {%4,%5,%6,%7}, {%8,%9}, {%0,%1,%2,%3};\n"
        : "+f"(c[0]), "+f"(c[1]), "+f"(c[2]), "+f"(c[3])
        : "r"(a0), "r"(a1), "r"(a2), "r"(a3), "r"(b0), "r"(b1));
}

// ---------------- CSR build ----------------
__global__ void k_zero() {
    PDL_TRIGGER();
    int i = blockIdx.x * blockDim.x + threadIdx.x;
    if (i < N_NODES) g_counts[i] = 0;
}

__global__ void k_hist(const int* __restrict__ dst) {
    PDL_TRIGGER();
    int e2 = blockIdx.x * blockDim.x + threadIdx.x;
    int2 d = make_int2(0, 0);
    bool ok = (2 * e2 < N_EDGES);
    if (ok) d = __ldg((const int2*)dst + e2);   // independent input: pre-wait
    PDL_WAIT();
    if (ok) {
        atomicAdd(&g_counts[d.x], 1);
        atomicAdd(&g_counts[d.y], 1);
    }
}

__global__ void k_scan_part() {
    PDL_TRIGGER();
    __shared__ int s[SCAN_B];
    int tid = threadIdx.x;
    int i = blockIdx.x * SCAN_B + tid;
    PDL_WAIT();
    int v = (i < N_NODES) ? g_counts[i] : 0;
    s[tid] = v;
    __syncthreads();
    for (int off = 1; off < SCAN_B; off <<= 1) {
        int t = (tid >= off) ? s[tid - off] : 0;
        __syncthreads();
        s[tid] += t;
        __syncthreads();
    }
    if (i < N_NODES) g_tmp[i] = s[tid];
    if (tid == SCAN_B - 1) g_bsum[blockIdx.x] = s[tid];
}

__global__ void k_scan_fin() {
    PDL_TRIGGER();
    __shared__ int soff;
    int tid = threadIdx.x;
    PDL_WAIT();
    if (tid < 32) {
        int v = 0;
        for (int j = tid; j < (int)blockIdx.x; j += 32) v += g_bsum[j];
#pragma unroll
        for (int o = 16; o > 0; o >>= 1) v += __shfl_xor_sync(0xffffffffu, v, o);
        if (tid == 0) soff = v;
    }
    __syncthreads();
    int off = soff;
    int i = blockIdx.x * SCAN_B + tid;
    if (i < N_NODES) {
        int incl = g_tmp[i] + off;
        int excl = incl - g_counts[i];
        g_rowptr[i] = excl;
        g_cursor[i] = excl;
        if (i == N_NODES - 1) g_rowptr[N_NODES] = incl;
    }
}

__global__ void k_scatter(const int* __restrict__ src, const int* __restrict__ dst,
                          const float* __restrict__ ew) {
    PDL_TRIGGER();
    int e2 = blockIdx.x * blockDim.x + threadIdx.x;
    bool ok = (2 * e2 < N_EDGES);
    int2 s = make_int2(0, 0), d = make_int2(0, 0);
    float2 w = make_float2(0.f, 0.f);
    if (ok) {                                  // independent inputs: pre-wait
        s = __ldg((const int2*)src + e2);
        d = __ldg((const int2*)dst + e2);
        w = __ldg((const float2*)ew + e2);
    }
    PDL_WAIT();
    if (ok) {
        int p0 = atomicAdd(&g_cursor[d.x], 1);
        g_edge[p0] = make_int2(s.x, __float_as_int(w.x));
        int p1 = atomicAdd(&g_cursor[d.y], 1);
        g_edge[p1] = make_int2(s.y, __float_as_int(w.y));
    }
}

// ---------------- aggregation: 2 nodes per warp, float4 lanes ---------------
__global__ void k_aggr64(int sel) {
    PDL_TRIGGER();
    PDL_WAIT();
    int gw   = (blockIdx.x * blockDim.x + threadIdx.x) >> 5;
    int lane = threadIdx.x & 31;
    int node = gw * 2 + (lane >> 4);
    int sl   = lane & 15;
    if (node >= N_NODES) return;
    const float4* __restrict__ h4 = (const float4*)g_h[sel];
    int e = g_rowptr[node], ee = g_rowptr[node + 1];
    float4 a0 = make_float4(0.f, 0.f, 0.f, 0.f);
    float4 a1 = make_float4(0.f, 0.f, 0.f, 0.f);
    for (; e + 4 <= ee; e += 4) {
        int2 r0 = __ldg(&g_edge[e + 0]);
        int2 r1 = __ldg(&g_edge[e + 1]);
        int2 r2 = __ldg(&g_edge[e + 2]);
        int2 r3 = __ldg(&g_edge[e + 3]);
        float4 v0 = __ldg(h4 + r0.x * 16 + sl);
        float4 v1 = __ldg(h4 + r1.x * 16 + sl);
        float4 v2 = __ldg(h4 + r2.x * 16 + sl);
        float4 v3 = __ldg(h4 + r3.x * 16 + sl);
        float w0 = __int_as_float(r0.y), w1 = __int_as_float(r1.y);
        float w2 = __int_as_float(r2.y), w3 = __int_as_float(r3.y);
        a0.x += w0 * v0.x + w1 * v1.x;  a0.y += w0 * v0.y + w1 * v1.y;
        a0.z += w0 * v0.z + w1 * v1.z;  a0.w += w0 * v0.w + w1 * v1.w;
        a1.x += w2 * v2.x + w3 * v3.x;  a1.y += w2 * v2.y + w3 * v3.y;
        a1.z += w2 * v2.z + w3 * v3.z;  a1.w += w2 * v2.w + w3 * v3.w;
    }
    for (; e < ee; e++) {
        int2 r = __ldg(&g_edge[e]);
        float4 v = __ldg(h4 + r.x * 16 + sl);
        float w = __int_as_float(r.y);
        a0.x += w * v.x; a0.y += w * v.y; a0.z += w * v.z; a0.w += w * v.w;
    }
    float4 o;
    o.x = a0.x + a1.x; o.y = a0.y + a1.y; o.z = a0.z + a1.z; o.w = a0.w + a1.w;
    ((float4*)g_aggr)[node * 16 + sl] = o;
}

// layer 0: 13-dim gather; 2 nodes/warp (13 of 16 lanes active per node)
__global__ void k_aggr13(const float* __restrict__ x) {
    PDL_TRIGGER();
    PDL_WAIT();
    int gw   = (blockIdx.x * blockDim.x + threadIdx.x) >> 5;
    int lane = threadIdx.x & 31;
    int node = gw * 2 + (lane >> 4);
    int sl   = lane & 15;
    if (node >= N_NODES) return;
    int e = g_rowptr[node], ee = g_rowptr[node + 1];
    float a = 0.f, b = 0.f;
    if (sl < 13) {
        for (; e + 2 <= ee; e += 2) {
            int2 r0 = __ldg(&g_edge[e + 0]);
            int2 r1 = __ldg(&g_edge[e + 1]);
            a += __int_as_float(r0.y) * __ldg(&x[r0.x * 13 + sl]);
            b += __int_as_float(r1.y) * __ldg(&x[r1.x * 13 + sl]);
        }
        if (e < ee) {
            int2 r = __ldg(&g_edge[e]);
            a += __int_as_float(r.y) * __ldg(&x[r.x * 13 + sl]);
        }
        g_aggr[node * 16 + sl] = a + b;
    }
}

// ---------------- GEMM 13->64 (FFMA; small) --------------------------------
__global__ __launch_bounds__(256) void k_gemm13(
    const float* __restrict__ x,
    const float* __restrict__ Wrel, const float* __restrict__ brel,
    const float* __restrict__ Wroot) {
    PDL_TRIGGER();
    __shared__ __align__(16) float sW[2 * 13 * 64];
    __shared__ float sb[64];
    int tid = threadIdx.x;
    for (int idx = tid; idx < 13 * 64; idx += 256) {   // independent inputs
        sW[idx]           = Wrel[idx];
        sW[13 * 64 + idx] = Wroot[idx];
    }
    if (tid < 64) sb[tid] = brel[tid];
    PDL_WAIT();
    __syncthreads();

    int node = blockIdx.x * 64 + (tid >> 2);
    int cq   = (tid & 3) * 4;
    int c0   = cq * 4;
    if (node >= N_NODES) return;
    float acc[16];
#pragma unroll
    for (int j = 0; j < 16; j++) acc[j] = sb[c0 + j];
    const float4* sWrel4  = (const float4*)sW;
    const float4* sWroot4 = (const float4*)(sW + 13 * 64);
#pragma unroll
    for (int k = 0; k < 13; k++) {
        float a  = __ldg(&g_aggr[node * 16 + k]);
        float hk = __ldg(&x[node * 13 + k]);
#pragma unroll
        for (int j = 0; j < 4; j++) {
            float4 wr = sWrel4[k * 16 + cq + j];
            float4 ws = sWroot4[k * 16 + cq + j];
            acc[4 * j + 0] += a * wr.x + hk * ws.x;
            acc[4 * j + 1] += a * wr.y + hk * ws.y;
            acc[4 * j + 2] += a * wr.z + hk * ws.z;
            acc[4 * j + 3] += a * wr.w + hk * ws.w;
        }
    }
    float4* o4 = (float4*)(g_h[0] + (long)node * 64 + c0);
#pragma unroll
    for (int j = 0; j < 4; j++) {
        float4 v;
        v.x = fmaxf(acc[4 * j + 0], 0.f); v.y = fmaxf(acc[4 * j + 1], 0.f);
        v.z = fmaxf(acc[4 * j + 2], 0.f); v.w = fmaxf(acc[4 * j + 3], 0.f);
        o4[j] = v;
    }
}

// ---------------- GEMM 64->64 via bf16 3-term MMA --------------------------
#define AW 68   // padded word stride (bank-conflict-free)
template <bool FINAL>
__global__ __launch_bounds__(256) void k_gemm64_mma(
    const float* __restrict__ Wrel, const float* __restrict__ brel,
    const float* __restrict__ Wroot,
    const float* __restrict__ Wrel4, const float* __restrict__ b4,
    const float* __restrict__ Wroot4,
    int insel, int outsel) {
    PDL_TRIGGER();
    extern __shared__ unsigned smem_u[];
    unsigned* sAhi = smem_u;                    // 128*AW
    unsigned* sAlo = sAhi + 128 * AW;           // 128*AW
    unsigned* sWhi = sAlo + 128 * AW;           // 64*AW
    unsigned* sWlo = sWhi + 64 * AW;            // 64*AW
    float*    sb   = (float*)(sWlo + 64 * AW);  // 64

    int tid = threadIdx.x;
    const float* __restrict__ hin = g_h[insel];
    int nbase = blockIdx.x * 128;

    if (tid < 64) sb[tid] = brel[tid];

    // stage W transposed (independent inputs -> pre-wait)
    for (int p = tid; p < 64 * 64; p += 256) {
        int col = p >> 6, w = p & 63;
        int k = 2 * w;
        float f0, f1;
        if (k < 64) { f0 = __ldg(&Wrel[k * 64 + col]);        f1 = __ldg(&Wrel[(k + 1) * 64 + col]); }
        else        { f0 = __ldg(&Wroot[(k - 64) * 64 + col]); f1 = __ldg(&Wroot[(k - 63) * 64 + col]); }
        unsigned h0 = bf16_rn(f0), h1 = bf16_rn(f1);
        float r0 = f0 - __uint_as_float(h0 << 16);
        float r1 = f1 - __uint_as_float(h1 << 16);
        sWhi[col * AW + w] = h0 | (h1 << 16);
        sWlo[col * AW + w] = bf16_rn(r0) | (bf16_rn(r1) << 16);
    }
    PDL_WAIT();
    // stage A: aggr -> words 0..31, h -> words 32..63 (dependent)
    for (int p = tid; p < 128 * 32; p += 256) {
        int ln = p >> 5, w = p & 31;
        int node = nbase + ln;
        if (node >= N_NODES) node = N_NODES - 1;
        float2 va = *(const float2*)(g_aggr + (size_t)node * 64 + 2 * w);
        float2 vh = *(const float2*)(hin    + (size_t)node * 64 + 2 * w);
        {
            unsigned h0 = bf16_rn(va.x), h1 = bf16_rn(va.y);
            sAhi[ln * AW + w] = h0 | (h1 << 16);
            sAlo[ln * AW + w] = bf16_rn(va.x - __uint_as_float(h0 << 16)) |
                                (bf16_rn(va.y - __uint_as_float(h1 << 16)) << 16);
        }
        {
            unsigned h0 = bf16_rn(vh.x), h1 = bf16_rn(vh.y);
            sAhi[ln * AW + 32 + w] = h0 | (h1 << 16);
            sAlo[ln * AW + 32 + w] = bf16_rn(vh.x - __uint_as_float(h0 << 16)) |
                                     (bf16_rn(vh.y - __uint_as_float(h1 << 16)) << 16);
        }
    }
    __syncthreads();

    int warp = tid >> 5, lane = tid & 31;
    int r = lane >> 2, q = lane & 3;
    int mb = warp * 16;

    float acc[8][4];
#pragma unroll
    for (int j = 0; j < 8; j++) {
        float b0 = sb[j * 8 + 2 * q], b1 = sb[j * 8 + 2 * q + 1];
        acc[j][0] = b0; acc[j][1] = b1; acc[j][2] = b0; acc[j][3] = b1;
    }

    int arow0 = (mb + r) * AW, arow1 = (mb + r + 8) * AW;
#pragma unroll
    for (int ks = 0; ks < 8; ks++) {
        int kw = ks * 8 + q;
        unsigned ah0 = sAhi[arow0 + kw],     ah1 = sAhi[arow1 + kw];
        unsigned ah2 = sAhi[arow0 + kw + 4], ah3 = sAhi[arow1 + kw + 4];
        unsigned al0 = sAlo[arow0 + kw],     al1 = sAlo[arow1 + kw];
        unsigned al2 = sAlo[arow0 + kw + 4], al3 = sAlo[arow1 + kw + 4];
#pragma unroll
        for (int j = 0; j < 8; j++) {
            int brow = (j * 8 + r) * AW + ks * 8 + q;
            unsigned bh0 = sWhi[brow], bh1 = sWhi[brow + 4];
            unsigned bl0 = sWlo[brow], bl1 = sWlo[brow + 4];
            mma_bf16(acc[j], ah0, ah1, ah2, ah3, bh0, bh1);
            mma_bf16(acc[j], ah0, ah1, ah2, ah3, bl0, bl1);
            mma_bf16(acc[j], al0, al1, al2, al3, bh0, bh1);
        }
    }

    int n0 = nbase + mb + r;      // row of c0/c1
    int n1 = n0 + 8;              // row of c2/c3
    if (FINAL) {
        float pt0 = 0.f, pr0 = 0.f, pt1 = 0.f, pr1 = 0.f;
#pragma unroll
        for (int j = 0; j < 8; j++) {
            int c = j * 8 + 2 * q;
            float w0 = __ldg(&Wrel4[c]),  w1 = __ldg(&Wrel4[c + 1]);
            float s0 = __ldg(&Wroot4[c]), s1 = __ldg(&Wroot4[c + 1]);
            float u;
            u = fmaxf(acc[j][0], 0.f); pt0 += u * w0; pr0 += u * s0;
            u = fmaxf(acc[j][1], 0.f); pt0 += u * w1; pr0 += u * s1;
            u = fmaxf(acc[j][2], 0.f); pt1 += u * w0; pr1 += u * s0;
            u = fmaxf(acc[j][3], 0.f); pt1 += u * w1; pr1 += u * s1;
        }
        pt0 += __shfl_xor_sync(0xffffffffu, pt0, 1);
        pt0 += __shfl_xor_sync(0xffffffffu, pt0, 2);
        pr0 += __shfl_xor_sync(0xffffffffu, pr0, 1);
        pr0 += __shfl_xor_sync(0xffffffffu, pr0, 2);
        pt1 += __shfl_xor_sync(0xffffffffu, pt1, 1);
        pt1 += __shfl_xor_sync(0xffffffffu, pt1, 2);
        pr1 += __shfl_xor_sync(0xffffffffu, pr1, 1);
        pr1 += __shfl_xor_sync(0xffffffffu, pr1, 2);
        float bb = __ldg(&b4[0]);
        if (q == 0) {
            if (n0 < N_NODES) { g_t[n0] = pt0; g_r[n0] = pr0 + bb; }
            if (n1 < N_NODES) { g_t[n1] = pt1; g_r[n1] = pr1 + bb; }
        }
    } else {
        float* ob = g_h[outsel];
#pragma unroll
        for (int j = 0; j < 8; j++) {
            int c = j * 8 + 2 * q;
            if (n0 < N_NODES)
                *(float2*)(ob + (size_t)n0 * 64 + c) =
                    make_float2(fmaxf(acc[j][0], 0.f), fmaxf(acc[j][1], 0.f));
            if (n1 < N_NODES)
                *(float2*)(ob + (size_t)n1 * 64 + c) =
                    make_float2(fmaxf(acc[j][2], 0.f), fmaxf(acc[j][3], 0.f));
        }
    }
}

// ---------------- final: out = sigmoid(segsum(w * t[src]) + r) -------------
__global__ void k_final(float* __restrict__ out) {
    PDL_TRIGGER();
    PDL_WAIT();
    int gw   = (blockIdx.x * blockDim.x + threadIdx.x) >> 5;
    int lane = threadIdx.x & 31;
    if (gw >= N_NODES) return;
    int start = g_rowptr[gw], end = g_rowptr[gw + 1];
    float acc = 0.f;
    for (int e = start + lane; e < end; e += 32) {
        int2 er = __ldg(&g_edge[e]);
        acc += __int_as_float(er.y) * __ldg(&g_t[er.x]);
    }
#pragma unroll
    for (int o = 16; o > 0; o >>= 1)
        acc += __shfl_xor_sync(0xffffffffu, acc, o);
    if (lane == 0) {
        float z = acc + g_r[gw];
        out[gw] = 1.f / (1.f + expf(-z));
    }
}

// ---------------- launch helpers ----------------
template <typename F, typename... Args>
static void launch_pdl(F f, dim3 g, dim3 b, size_t sm, Args... args) {
    cudaLaunchConfig_t cfg = {};
    cfg.gridDim = g;
    cfg.blockDim = b;
    cfg.dynamicSmemBytes = sm;
    cfg.stream = 0;
    cudaLaunchAttribute at[1];
    at[0].id = cudaLaunchAttributeProgrammaticStreamSerialization;
    at[0].val.programmaticStreamSerializationAllowed = 1;
    cfg.attrs = at;
    cfg.numAttrs = 1;
    cudaLaunchKernelEx(&cfg, f, args...);
}

extern "C" void kernel_launch(void* const* d_in, const int* in_sizes, int n_in,
                              void* d_out, int out_size) {
    const float* x  = (const float*)d_in[0];
    const int*   ei = (const int*)d_in[1];
    const float* ew = (const float*)d_in[2];
    const int* src = ei;
    const int* dst = ei + N_EDGES;

    const float* Wrel[5], * brel[5], * Wroot[5];
    for (int l = 0; l < 5; l++) {
        Wrel[l]  = (const float*)d_in[3 + 3 * l];
        brel[l]  = (const float*)d_in[4 + 3 * l];
        Wroot[l] = (const float*)d_in[5 + 3 * l];
    }
    float* out = (float*)d_out;

    const int SMEM_MMA = (128 * AW * 2 + 64 * AW * 2 + 64) * 4;   // 104704 B
    cudaFuncSetAttribute(k_gemm64_mma<false>,
                         cudaFuncAttributeMaxDynamicSharedMemorySize, SMEM_MMA);
    cudaFuncSetAttribute(k_gemm64_mma<true>,
                         cudaFuncAttributeMaxDynamicSharedMemorySize, SMEM_MMA);

    const int TB = 256;
    dim3 B(TB);
    int gN   = (N_NODES + TB - 1) / TB;
    int gE2  = (N_EDGES / 2 + TB - 1) / TB;       // 2 edges/thread
    int gW   = (N_NODES * 32 + TB - 1) / TB;      // warp-per-node (k_final)
    int gW2  = (N_NODES * 16 + TB - 1) / TB;      // 2 nodes/warp (aggr)
    int g64  = (N_NODES + 63) / 64;
    int g128 = (N_NODES + 127) / 128;

    // CSR build
    k_zero<<<gN, TB>>>();
    launch_pdl(k_hist, dim3(gE2), B, 0, dst);
    launch_pdl(k_scan_part, dim3(SCAN_NB), dim3(SCAN_B), 0);
    launch_pdl(k_scan_fin,  dim3(SCAN_NB), dim3(SCAN_B), 0);
    launch_pdl(k_scatter, dim3(gE2), B, 0, src, dst, ew);

    // layer 0: 13 -> 64
    launch_pdl(k_aggr13, dim3(gW2), B, 0, x);
    launch_pdl(k_gemm13, dim3(g64), B, 0, x, Wrel[0], brel[0], Wroot[0]);

    // layers 1-3: 64 -> 64 (layer 3 folds the 64->1 projection of layer 4)
    launch_pdl(k_aggr64, dim3(gW2), B, 0, 0);
    launch_pdl(k_gemm64_mma<false>, dim3(g128), B, (size_t)SMEM_MMA,
               Wrel[1], brel[1], Wroot[1],
               (const float*)nullptr, (const float*)nullptr, (const float*)nullptr, 0, 1);
    launch_pdl(k_aggr64, dim3(gW2), B, 0, 1);
    launch_pdl(k_gemm64_mma<false>, dim3(g128), B, (size_t)SMEM_MMA,
               Wrel[2], brel[2], Wroot[2],
               (const float*)nullptr, (const float*)nullptr, (const float*)nullptr, 1, 0);
    launch_pdl(k_aggr64, dim3(gW2), B, 0, 0);
    launch_pdl(k_gemm64_mma<true>, dim3(g128), B, (size_t)SMEM_MMA,
               Wrel[3], brel[3], Wroot[3],
               Wrel[4], brel[4], Wroot[4], 0, 0);

    // layer 4 aggregation (scalar) + sigmoid
    launch_pdl(k_final, dim3(gW), B, 0, out);
}

// round 6
// speedup vs baseline: 2.4444x; 1.0050x over previous
#include <cuda_runtime.h>
#include <math.h>

#define N_NODES 50000
#define N_EDGES 800000
#define SCAN_B  1024
#define SCAN_NB ((N_NODES + SCAN_B - 1) / SCAN_B)   // 49

// griddepcontrol (PDL)
#define PDL_TRIGGER() asm volatile("griddepcontrol.launch_dependents;" ::: "memory")
#define PDL_WAIT()    asm volatile("griddepcontrol.wait;" ::: "memory")

// ---------------- scratch (static device memory; no allocs) ----------------
__device__ int   g_counts[N_NODES];        // invariant: zero at kernel_launch entry
__device__ int   g_rowptr[N_NODES + 1];
__device__ int   g_cursor[N_NODES];
__device__ int   g_tmp[N_NODES];
__device__ int   g_bsum[SCAN_NB];
__device__ int2  g_edge[N_EDGES];          // {src, weight-as-int}
__device__ float g_x16[N_NODES * 16];      // x padded 13 -> 16
__device__ float g_h[2][N_NODES * 64];
__device__ float g_aggr[N_NODES * 64];     // also holds 16-stride layer0 aggr
__device__ float g_t[N_NODES];
__device__ float g_r[N_NODES];

// ---------------- helpers ----------------
__device__ __forceinline__ unsigned bf16_rn(float f) {
    unsigned u = __float_as_uint(f);
    return (u + 0x7fffu + ((u >> 16) & 1u)) >> 16;
}

__device__ __forceinline__ void mma_bf16(float* c,
                                         unsigned a0, unsigned a1, unsigned a2, unsigned a3,
                                         unsigned b0, unsigned b1) {
    asm volatile(
        "mma.sync.aligned.m16n8k16.row.col.f32.bf16.bf16.f32 "
        "{%0,%1,%2,%3}, {%4,%5,%6,%7}, {%8,%9}, {%0,%1,%2,%3};\n"
        : "+f"(c[0]), "+f"(c[1]), "+f"(c[2]), "+f"(c[3])
        : "r"(a0), "r"(a1), "r"(a2), "r"(a3), "r"(b0), "r"(b1));
}

// ---------------- x padding (input-only; first in chain) -------------------
__global__ void k_padx(const float* __restrict__ x) {
    PDL_TRIGGER();
    int i = blockIdx.x * blockDim.x + threadIdx.x;   // float4 index
    if (i >= N_NODES * 4) return;
    int node = i >> 2, c = (i & 3) * 4;
    float4 v;
    v.x = (c + 0 < 13) ? __ldg(&x[node * 13 + c + 0]) : 0.f;
    v.y = (c + 1 < 13) ? __ldg(&x[node * 13 + c + 1]) : 0.f;
    v.z = (c + 2 < 13) ? __ldg(&x[node * 13 + c + 2]) : 0.f;
    v.w = (c + 3 < 13) ? __ldg(&x[node * 13 + c + 3]) : 0.f;
    ((float4*)g_x16)[i] = v;
}

// ---------------- CSR build ----------------
__global__ void k_hist(const int* __restrict__ dst) {
    PDL_TRIGGER();
    int e2 = blockIdx.x * blockDim.x + threadIdx.x;
    int2 d = make_int2(0, 0);
    bool ok = (2 * e2 < N_EDGES);
    if (ok) d = __ldg((const int2*)dst + e2);   // harness input: pre-wait safe
    PDL_WAIT();
    if (ok) {
        atomicAdd(&g_counts[d.x], 1);
        atomicAdd(&g_counts[d.y], 1);
    }
}

// shfl-based scan: 2 barriers instead of 20
__global__ void k_scan_part() {
    PDL_TRIGGER();
    __shared__ int swarp[32];
    int tid = threadIdx.x, lane = tid & 31, wid = tid >> 5;
    int i = blockIdx.x * SCAN_B + tid;
    PDL_WAIT();
    int v = (i < N_NODES) ? g_counts[i] : 0;
#pragma unroll
    for (int o = 1; o < 32; o <<= 1) {
        int t = __shfl_up_sync(0xffffffffu, v, o);
        if (lane >= o) v += t;
    }
    if (lane == 31) swarp[wid] = v;
    __syncthreads();
    if (wid == 0) {
        int w = swarp[lane];
#pragma unroll
        for (int o = 1; o < 32; o <<= 1) {
            int t = __shfl_up_sync(0xffffffffu, w, o);
            if (lane >= o) w += t;
        }
        swarp[lane] = w;
    }
    __syncthreads();
    if (wid > 0) v += swarp[wid - 1];
    if (i < N_NODES) g_tmp[i] = v;
    if (tid == SCAN_B - 1) g_bsum[blockIdx.x] = v;
}

__global__ void k_scan_fin() {
    PDL_TRIGGER();
    __shared__ int soff;
    int tid = threadIdx.x;
    PDL_WAIT();
    if (tid < 32) {
        int v = 0;
        for (int j = tid; j < (int)blockIdx.x; j += 32) v += g_bsum[j];
#pragma unroll
        for (int o = 16; o > 0; o >>= 1) v += __shfl_xor_sync(0xffffffffu, v, o);
        if (tid == 0) soff = v;
    }
    __syncthreads();
    int off = soff;
    int i = blockIdx.x * SCAN_B + tid;
    if (i < N_NODES) {
        int incl = g_tmp[i] + off;
        int c = g_counts[i];
        int excl = incl - c;
        g_rowptr[i] = excl;
        g_cursor[i] = excl;
        g_counts[i] = 0;                 // restore invariant for next replay
        if (i == N_NODES - 1) g_rowptr[N_NODES] = incl;
    }
}

__global__ void k_scatter(const int* __restrict__ src, const int* __restrict__ dst,
                          const float* __restrict__ ew) {
    PDL_TRIGGER();
    int e2 = blockIdx.x * blockDim.x + threadIdx.x;
    bool ok = (2 * e2 < N_EDGES);
    int2 s = make_int2(0, 0), d = make_int2(0, 0);
    float2 w = make_float2(0.f, 0.f);
    if (ok) {                                  // harness inputs: pre-wait safe
        s = __ldg((const int2*)src + e2);
        d = __ldg((const int2*)dst + e2);
        w = __ldg((const float2*)ew + e2);
    }
    PDL_WAIT();
    if (ok) {
        int p0 = atomicAdd(&g_cursor[d.x], 1);
        g_edge[p0] = make_int2(s.x, __float_as_int(w.x));
        int p1 = atomicAdd(&g_cursor[d.y], 1);
        g_edge[p1] = make_int2(s.y, __float_as_int(w.y));
    }
}

// ---------------- aggregation: full warp per node --------------------------
// halves take alternate edges of the SAME node -> no divergence waste;
// each half covers the full 64-float row (16 lanes x float4).
__global__ void k_aggr64(int sel) {
    PDL_TRIGGER();
    PDL_WAIT();
    int w = (blockIdx.x * blockDim.x + threadIdx.x) >> 5;
    if (w >= N_NODES) return;
    int lane = threadIdx.x & 31, half = lane >> 4, sl = lane & 15;
    const float4* __restrict__ h4 = (const float4*)g_h[sel];
    int i = g_rowptr[w] + half, e = g_rowptr[w + 1];
    float4 a = make_float4(0.f, 0.f, 0.f, 0.f);
    float4 b = make_float4(0.f, 0.f, 0.f, 0.f);
    for (; i + 2 < e; i += 4) {
        int2 r0 = __ldg(&g_edge[i]);
        int2 r1 = __ldg(&g_edge[i + 2]);
        float4 v0 = __ldg(h4 + r0.x * 16 + sl);
        float4 v1 = __ldg(h4 + r1.x * 16 + sl);
        float w0 = __int_as_float(r0.y), w1 = __int_as_float(r1.y);
        a.x += w0 * v0.x; a.y += w0 * v0.y; a.z += w0 * v0.z; a.w += w0 * v0.w;
        b.x += w1 * v1.x; b.y += w1 * v1.y; b.z += w1 * v1.z; b.w += w1 * v1.w;
    }
    if (i < e) {
        int2 r = __ldg(&g_edge[i]);
        float4 v = __ldg(h4 + r.x * 16 + sl);
        float ww = __int_as_float(r.y);
        a.x += ww * v.x; a.y += ww * v.y; a.z += ww * v.z; a.w += ww * v.w;
    }
    a.x += b.x; a.y += b.y; a.z += b.z; a.w += b.w;
    a.x += __shfl_xor_sync(0xffffffffu, a.x, 16);
    a.y += __shfl_xor_sync(0xffffffffu, a.y, 16);
    a.z += __shfl_xor_sync(0xffffffffu, a.z, 16);
    a.w += __shfl_xor_sync(0xffffffffu, a.w, 16);
    if (half == 0) ((float4*)(g_aggr + (size_t)w * 64))[sl] = a;
}

// layer 0: warp per node, 8 edge-slots x 4 lanes x float4 over padded x16
__global__ void k_aggr13() {
    PDL_TRIGGER();
    PDL_WAIT();
    int w = (blockIdx.x * blockDim.x + threadIdx.x) >> 5;
    if (w >= N_NODES) return;
    int lane = threadIdx.x & 31, grp = lane >> 2, sl = lane & 3;
    const float4* __restrict__ x4 = (const float4*)g_x16;
    int i = g_rowptr[w] + grp, e = g_rowptr[w + 1];
    float4 a = make_float4(0.f, 0.f, 0.f, 0.f);
    for (; i < e; i += 8) {
        int2 r = __ldg(&g_edge[i]);
        float4 v = __ldg(x4 + r.x * 4 + sl);
        float ww = __int_as_float(r.y);
        a.x += ww * v.x; a.y += ww * v.y; a.z += ww * v.z; a.w += ww * v.w;
    }
#pragma unroll
    for (int o = 4; o < 32; o <<= 1) {
        a.x += __shfl_xor_sync(0xffffffffu, a.x, o);
        a.y += __shfl_xor_sync(0xffffffffu, a.y, o);
        a.z += __shfl_xor_sync(0xffffffffu, a.z, o);
        a.w += __shfl_xor_sync(0xffffffffu, a.w, o);
    }
    if (grp == 0) ((float4*)(g_aggr + (size_t)w * 16))[sl] = a;
}

// ---------------- GEMM 13->64 (FFMA; small) --------------------------------
__global__ __launch_bounds__(256) void k_gemm13(
    const float* __restrict__ x,
    const float* __restrict__ Wrel, const float* __restrict__ brel,
    const float* __restrict__ Wroot) {
    PDL_TRIGGER();
    __shared__ __align__(16) float sW[2 * 13 * 64];
    __shared__ float sb[64];
    int tid = threadIdx.x;
    for (int idx = tid; idx < 13 * 64; idx += 256) {   // harness inputs
        sW[idx]           = Wrel[idx];
        sW[13 * 64 + idx] = Wroot[idx];
    }
    if (tid < 64) sb[tid] = brel[tid];
    PDL_WAIT();
    __syncthreads();

    int node = blockIdx.x * 64 + (tid >> 2);
    int cq   = (tid & 3) * 4;
    int c0   = cq * 4;
    if (node >= N_NODES) return;
    float acc[16];
#pragma unroll
    for (int j = 0; j < 16; j++) acc[j] = sb[c0 + j];
    const float4* sWrel4  = (const float4*)sW;
    const float4* sWroot4 = (const float4*)(sW + 13 * 64);
#pragma unroll
    for (int k = 0; k < 13; k++) {
        float a  = __ldg(&g_aggr[node * 16 + k]);
        float hk = __ldg(&x[node * 13 + k]);
#pragma unroll
        for (int j = 0; j < 4; j++) {
            float4 wr = sWrel4[k * 16 + cq + j];
            float4 ws = sWroot4[k * 16 + cq + j];
            acc[4 * j + 0] += a * wr.x + hk * ws.x;
            acc[4 * j + 1] += a * wr.y + hk * ws.y;
            acc[4 * j + 2] += a * wr.z + hk * ws.z;
            acc[4 * j + 3] += a * wr.w + hk * ws.w;
        }
    }
    float4* o4 = (float4*)(g_h[0] + (long)node * 64 + c0);
#pragma unroll
    for (int j = 0; j < 4; j++) {
        float4 v;
        v.x = fmaxf(acc[4 * j + 0], 0.f); v.y = fmaxf(acc[4 * j + 1], 0.f);
        v.z = fmaxf(acc[4 * j + 2], 0.f); v.w = fmaxf(acc[4 * j + 3], 0.f);
        o4[j] = v;
    }
}

// ---------------- GEMM 64->64 via bf16 3-term MMA --------------------------
#define AW 68   // padded word stride (bank-conflict-free)
template <bool FINAL>
__global__ __launch_bounds__(256) void k_gemm64_mma(
    const float* __restrict__ Wrel, const float* __restrict__ brel,
    const float* __restrict__ Wroot,
    const float* __restrict__ Wrel4, const float* __restrict__ b4,
    const float* __restrict__ Wroot4,
    int insel, int outsel) {
    PDL_TRIGGER();
    extern __shared__ unsigned smem_u[];
    unsigned* sAhi = smem_u;                    // 128*AW
    unsigned* sAlo = sAhi + 128 * AW;           // 128*AW
    unsigned* sWhi = sAlo + 128 * AW;           // 64*AW
    unsigned* sWlo = sWhi + 64 * AW;            // 64*AW
    float*    sb   = (float*)(sWlo + 64 * AW);  // 64

    int tid = threadIdx.x;
    const float* __restrict__ hin = g_h[insel];
    int nbase = blockIdx.x * 128;

    if (tid < 64) sb[tid] = brel[tid];

    // stage W transposed (harness inputs -> pre-wait)
    for (int p = tid; p < 64 * 64; p += 256) {
        int col = p >> 6, w = p & 63;
        int k = 2 * w;
        float f0, f1;
        if (k < 64) { f0 = __ldg(&Wrel[k * 64 + col]);        f1 = __ldg(&Wrel[(k + 1) * 64 + col]); }
        else        { f0 = __ldg(&Wroot[(k - 64) * 64 + col]); f1 = __ldg(&Wroot[(k - 63) * 64 + col]); }
        unsigned h0 = bf16_rn(f0), h1 = bf16_rn(f1);
        float r0 = f0 - __uint_as_float(h0 << 16);
        float r1 = f1 - __uint_as_float(h1 << 16);
        sWhi[col * AW + w] = h0 | (h1 << 16);
        sWlo[col * AW + w] = bf16_rn(r0) | (bf16_rn(r1) << 16);
    }
    PDL_WAIT();
    // stage A: aggr -> words 0..31, h -> words 32..63 (dependent)
    for (int p = tid; p < 128 * 32; p += 256) {
        int ln = p >> 5, w = p & 31;
        int node = nbase + ln;
        if (node >= N_NODES) node = N_NODES - 1;
        float2 va = *(const float2*)(g_aggr + (size_t)node * 64 + 2 * w);
        float2 vh = *(const float2*)(hin    + (size_t)node * 64 + 2 * w);
        {
            unsigned h0 = bf16_rn(va.x), h1 = bf16_rn(va.y);
            sAhi[ln * AW + w] = h0 | (h1 << 16);
            sAlo[ln * AW + w] = bf16_rn(va.x - __uint_as_float(h0 << 16)) |
                                (bf16_rn(va.y - __uint_as_float(h1 << 16)) << 16);
        }
        {
            unsigned h0 = bf16_rn(vh.x), h1 = bf16_rn(vh.y);
            sAhi[ln * AW + 32 + w] = h0 | (h1 << 16);
            sAlo[ln * AW + 32 + w] = bf16_rn(vh.x - __uint_as_float(h0 << 16)) |
                                     (bf16_rn(vh.y - __uint_as_float(h1 << 16)) << 16);
        }
    }
    __syncthreads();

    int warp = tid >> 5, lane = tid & 31;
    int r = lane >> 2, q = lane & 3;
    int mb = warp * 16;

    float acc[8][4];
#pragma unroll
    for (int j = 0; j < 8; j++) {
        float b0 = sb[j * 8 + 2 * q], b1 = sb[j * 8 + 2 * q + 1];
        acc[j][0] = b0; acc[j][1] = b1; acc[j][2] = b0; acc[j][3] = b1;
    }

    int arow0 = (mb + r) * AW, arow1 = (mb + r + 8) * AW;
#pragma unroll
    for (int ks = 0; ks < 8; ks++) {
        int kw = ks * 8 + q;
        unsigned ah0 = sAhi[arow0 + kw],     ah1 = sAhi[arow1 + kw];
        unsigned ah2 = sAhi[arow0 + kw + 4], ah3 = sAhi[arow1 + kw + 4];
        unsigned al0 = sAlo[arow0 + kw],     al1 = sAlo[arow1 + kw];
        unsigned al2 = sAlo[arow0 + kw + 4], al3 = sAlo[arow1 + kw + 4];
#pragma unroll
        for (int j = 0; j < 8; j++) {
            int brow = (j * 8 + r) * AW + ks * 8 + q;
            unsigned bh0 = sWhi[brow], bh1 = sWhi[brow + 4];
            unsigned bl0 = sWlo[brow], bl1 = sWlo[brow + 4];
            mma_bf16(acc[j], ah0, ah1, ah2, ah3, bh0, bh1);
            mma_bf16(acc[j], ah0, ah1, ah2, ah3, bl0, bl1);
            mma_bf16(acc[j], al0, al1, al2, al3, bh0, bh1);
        }
    }

    int n0 = nbase + mb + r;      // row of c0/c1
    int n1 = n0 + 8;              // row of c2/c3
    if (FINAL) {
        float pt0 = 0.f, pr0 = 0.f, pt1 = 0.f, pr1 = 0.f;
#pragma unroll
        for (int j = 0; j < 8; j++) {
            int c = j * 8 + 2 * q;
            float w0 = __ldg(&Wrel4[c]),  w1 = __ldg(&Wrel4[c + 1]);
            float s0 = __ldg(&Wroot4[c]), s1 = __ldg(&Wroot4[c + 1]);
            float u;
            u = fmaxf(acc[j][0], 0.f); pt0 += u * w0; pr0 += u * s0;
            u = fmaxf(acc[j][1], 0.f); pt0 += u * w1; pr0 += u * s1;
            u = fmaxf(acc[j][2], 0.f); pt1 += u * w0; pr1 += u * s0;
            u = fmaxf(acc[j][3], 0.f); pt1 += u * w1; pr1 += u * s1;
        }
        pt0 += __shfl_xor_sync(0xffffffffu, pt0, 1);
        pt0 += __shfl_xor_sync(0xffffffffu, pt0, 2);
        pr0 += __shfl_xor_sync(0xffffffffu, pr0, 1);
        pr0 += __shfl_xor_sync(0xffffffffu, pr0, 2);
        pt1 += __shfl_xor_sync(0xffffffffu, pt1, 1);
        pt1 += __shfl_xor_sync(0xffffffffu, pt1, 2);
        pr1 += __shfl_xor_sync(0xffffffffu, pr1, 1);
        pr1 += __shfl_xor_sync(0xffffffffu, pr1, 2);
        float bb = __ldg(&b4[0]);
        if (q == 0) {
            if (n0 < N_NODES) { g_t[n0] = pt0; g_r[n0] = pr0 + bb; }
            if (n1 < N_NODES) { g_t[n1] = pt1; g_r[n1] = pr1 + bb; }
        }
    } else {
        float* ob = g_h[outsel];
#pragma unroll
        for (int j = 0; j < 8; j++) {
            int c = j * 8 + 2 * q;
            if (n0 < N_NODES)
                *(float2*)(ob + (size_t)n0 * 64 + c) =
                    make_float2(fmaxf(acc[j][0], 0.f), fmaxf(acc[j][1], 0.f));
            if (n1 < N_NODES)
                *(float2*)(ob + (size_t)n1 * 64 + c) =
                    make_float2(fmaxf(acc[j][2], 0.f), fmaxf(acc[j][3], 0.f));
        }
    }
}

// ---------------- final: out = sigmoid(segsum(w * t[src]) + r) -------------
__global__ void k_final(float* __restrict__ out) {
    PDL_TRIGGER();
    PDL_WAIT();
    int gw   = (blockIdx.x * blockDim.x + threadIdx.x) >> 5;
    int lane = threadIdx.x & 31;
    if (gw >= N_NODES) return;
    int start = g_rowptr[gw], end = g_rowptr[gw + 1];
    float acc = 0.f;
    for (int e = start + lane; e < end; e += 32) {
        int2 er = __ldg(&g_edge[e]);
        acc += __int_as_float(er.y) * __ldg(&g_t[er.x]);
    }
#pragma unroll
    for (int o = 16; o > 0; o >>= 1)
        acc += __shfl_xor_sync(0xffffffffu, acc, o);
    if (lane == 0) {
        float z = acc + g_r[gw];
        out[gw] = 1.f / (1.f + expf(-z));
    }
}

// ---------------- launch helpers ----------------
template <typename F, typename... Args>
static void launch_pdl(F f, dim3 g, dim3 b, size_t sm, Args... args) {
    cudaLaunchConfig_t cfg = {};
    cfg.gridDim = g;
    cfg.blockDim = b;
    cfg.dynamicSmemBytes = sm;
    cfg.stream = 0;
    cudaLaunchAttribute at[1];
    at[0].id = cudaLaunchAttributeProgrammaticStreamSerialization;
    at[0].val.programmaticStreamSerializationAllowed = 1;
    cfg.attrs = at;
    cfg.numAttrs = 1;
    cudaLaunchKernelEx(&cfg, f, args...);
}

extern "C" void kernel_launch(void* const* d_in, const int* in_sizes, int n_in,
                              void* d_out, int out_size) {
    const float* x  = (const float*)d_in[0];
    const int*   ei = (const int*)d_in[1];
    const float* ew = (const float*)d_in[2];
    const int* src = ei;
    const int* dst = ei + N_EDGES;

    const float* Wrel[5], * brel[5], * Wroot[5];
    for (int l = 0; l < 5; l++) {
        Wrel[l]  = (const float*)d_in[3 + 3 * l];
        brel[l]  = (const float*)d_in[4 + 3 * l];
        Wroot[l] = (const float*)d_in[5 + 3 * l];
    }
    float* out = (float*)d_out;

    const int SMEM_MMA = (128 * AW * 2 + 64 * AW * 2 + 64) * 4;   // 104704 B
    cudaFuncSetAttribute(k_gemm64_mma<false>,
                         cudaFuncAttributeMaxDynamicSharedMemorySize, SMEM_MMA);
    cudaFuncSetAttribute(k_gemm64_mma<true>,
                         cudaFuncAttributeMaxDynamicSharedMemorySize, SMEM_MMA);

    const int TB = 256;
    dim3 B(TB);
    int gP   = (N_NODES * 4 + TB - 1) / TB;       // padx
    int gE2  = (N_EDGES / 2 + TB - 1) / TB;       // 2 edges/thread
    int gW   = (N_NODES * 32 + TB - 1) / TB;      // warp-per-node
    int g64  = (N_NODES + 63) / 64;
    int g128 = (N_NODES + 127) / 128;

    // x padding (input-only) then CSR build (g_counts is zero by invariant)
    launch_pdl(k_padx, dim3(gP), B, 0, x);
    launch_pdl(k_hist, dim3(gE2), B, 0, dst);
    launch_pdl(k_scan_part, dim3(SCAN_NB), dim3(SCAN_B), 0);
    launch_pdl(k_scan_fin,  dim3(SCAN_NB), dim3(SCAN_B), 0);
    launch_pdl(k_scatter, dim3(gE2), B, 0, src, dst, ew);

    // layer 0: 13 -> 64
    launch_pdl(k_aggr13, dim3(gW), B, 0);
    launch_pdl(k_gemm13, dim3(g64), B, 0, x, Wrel[0], brel[0], Wroot[0]);

    // layers 1-3: 64 -> 64 (layer 3 folds the 64->1 projection of layer 4)
    launch_pdl(k_aggr64, dim3(gW), B, 0, 0);
    launch_pdl(k_gemm64_mma<false>, dim3(g128), B, (size_t)SMEM_MMA,
               Wrel[1], brel[1], Wroot[1],
               (const float*)nullptr, (const float*)nullptr, (const float*)nullptr, 0, 1);
    launch_pdl(k_aggr64, dim3(gW), B, 0, 1);
    launch_pdl(k_gemm64_mma<false>, dim3(g128), B, (size_t)SMEM_MMA,
               Wrel[2], brel[2], Wroot[2],
               (const float*)nullptr, (const float*)nullptr, (const float*)nullptr, 1, 0);
    launch_pdl(k_aggr64, dim3(gW), B, 0, 0);
    launch_pdl(k_gemm64_mma<true>, dim3(g128), B, (size_t)SMEM_MMA,
               Wrel[3], brel[3], Wroot[3],
               Wrel[4], brel[4], Wroot[4], 0, 0);

    // layer 4 aggregation (scalar) + sigmoid
    launch_pdl(k_final, dim3(gW), B, 0, out);
}